// round 6
// baseline (speedup 1.0000x reference)
#include <cuda_runtime.h>
#include <cuda_bf16.h>
#include <cstdint>

#define NB 16
#define NS 2048
#define NE 1024
#define NH 4
#define ND 256
#define NBH 64
#define BK 32

// ---------------- device scratch ------------------------------------------------
__device__ __align__(16) __nv_bfloat16 gXb[(size_t)NB * NS * NE];
__device__ __align__(16) __nv_bfloat16 gWb[(size_t)2 * NE * NE];
__device__ __align__(16) __nv_bfloat16 gQ[(size_t)NBH * NS * ND];   // scaled by 1/16
__device__ __align__(16) __nv_bfloat16 gK[(size_t)NBH * NS * ND];
__device__ __align__(16) __nv_bfloat16 gP[(size_t)NBH * NS * NS];   // exp(scores)
__device__ float gL[NBH * NS];
__device__ float gLinv[NBH * NS];
__device__ float gColsum[NBH * NS];
__device__ float gCs[NB * NS];
__device__ float gG[NBH * NS];
__device__ float gSg[NBH];
__device__ float gU[NBH * NE];
__device__ float gY[NB * NE];
__device__ unsigned char gValid[NB * NS];
__device__ int gLen[NB];
__device__ int gEnc;

// ---------------- helpers ---------------------------------------------------------
__device__ __forceinline__ void cpa16(uint32_t s, const void* g) {
    asm volatile("cp.async.cg.shared.global [%0], [%1], 16;\n" :: "r"(s), "l"(g));
}
__device__ __forceinline__ void cp_commit() { asm volatile("cp.async.commit_group;\n"); }
template <int N>
__device__ __forceinline__ void cp_wait() { asm volatile("cp.async.wait_group %0;\n" :: "n"(N)); }

__device__ __forceinline__ void ldm4(uint32_t (&r)[4], uint32_t addr) {
    asm volatile("ldmatrix.sync.aligned.m8n8.x4.shared.b16 {%0,%1,%2,%3}, [%4];"
                 : "=r"(r[0]), "=r"(r[1]), "=r"(r[2]), "=r"(r[3]) : "r"(addr));
}

__device__ __forceinline__ void mma16816(float (&d)[4], const uint32_t (&a)[4],
                                         uint32_t b0, uint32_t b1) {
    asm volatile("mma.sync.aligned.m16n8k16.row.col.f32.bf16.bf16.f32 "
                 "{%0,%1,%2,%3}, {%4,%5,%6,%7}, {%8,%9}, {%0,%1,%2,%3};"
                 : "+f"(d[0]), "+f"(d[1]), "+f"(d[2]), "+f"(d[3])
                 : "r"(a[0]), "r"(a[1]), "r"(a[2]), "r"(a[3]), "r"(b0), "r"(b1));
}

// 64B-row swizzle: rows of 32 bf16, 4 chunks of 16B. chunk' = c ^ ((row>>1)&3)
__device__ __forceinline__ uint32_t swz64(uint32_t row, uint32_t c16) {
    return row * 64u + ((c16 ^ ((row >> 1) & 3u)) << 4);
}

// one pipeline stage: A 128x32 bf16 (8KB) + B 128x32 bf16 (8KB), 128 threads
__device__ __forceinline__ void load_stage(uint32_t sA, uint32_t sB,
                                           const __nv_bfloat16* __restrict__ Ag,
                                           const __nv_bfloat16* __restrict__ Bg,
                                           int lda, int tid) {
#pragma unroll
    for (int i = 0; i < 4; i++) {
        int ci = i * 128 + tid;
        uint32_t row = ci >> 2, c16 = ci & 3;
        cpa16(sA + swz64(row, c16), Ag + (size_t)row * lda + c16 * 8);
        cpa16(sB + swz64(row, c16), Bg + (size_t)row * lda + c16 * 8);
    }
}

// 128x128 block, 128 threads = 4 warps (2x2), warp tile 64x64, 4-stage pipeline.
template <int KIT>
__device__ __forceinline__ void gemm_core(const __nv_bfloat16* __restrict__ A,
                                          const __nv_bfloat16* __restrict__ B,
                                          int lda, float (&c)[4][8][4], char* dsm) {
    uint32_t s0;
    asm("{ .reg .u64 t; cvta.to.shared.u64 t, %1; cvt.u32.u64 %0, t; }" : "=r"(s0) : "l"(dsm));
    const int tid = threadIdx.x, lane = tid & 31, warp = tid >> 5;
    const int wm = warp >> 1, wn = warp & 1;

#pragma unroll
    for (int s = 0; s < 3; s++) {
        if (s < KIT)
            load_stage(s0 + s * 16384, s0 + s * 16384 + 8192,
                       A + s * BK, B + s * BK, lda, tid);
        cp_commit();
    }

    for (int kt = 0; kt < KIT; kt++) {
        cp_wait<2>();
        __syncthreads();
        if (kt + 3 < KIT)
            load_stage(s0 + ((kt + 3) & 3) * 16384, s0 + ((kt + 3) & 3) * 16384 + 8192,
                       A + (size_t)(kt + 3) * BK, B + (size_t)(kt + 3) * BK, lda, tid);
        cp_commit();

        uint32_t aB = s0 + (kt & 3) * 16384;
        uint32_t bB = aB + 8192;
#pragma unroll
        for (int ks = 0; ks < 2; ks++) {
            uint32_t c16 = ks * 2 + (lane >> 4);
            uint32_t a[4][4];
#pragma unroll
            for (int mi = 0; mi < 4; mi++)
                ldm4(a[mi], aB + swz64(wm * 64 + mi * 16 + (lane & 15), c16));
            uint32_t b[8][2];
#pragma unroll
            for (int p = 0; p < 4; p++) {
                uint32_t q[4];
                ldm4(q, bB + swz64(wn * 64 + p * 16 + (lane & 15), c16));
                b[p * 2 + 0][0] = q[0]; b[p * 2 + 0][1] = q[2];
                b[p * 2 + 1][0] = q[1]; b[p * 2 + 1][1] = q[3];
            }
#pragma unroll
            for (int mi = 0; mi < 4; mi++)
#pragma unroll
                for (int ni = 0; ni < 8; ni++)
                    mma16816(c[mi][ni], a[mi], b[ni][0], b[ni][1]);
        }
    }
}

// ---------------- mask handling -----------------------------------------------------
__global__ void k_classify(const unsigned* __restrict__ m) {
    __shared__ int ok[3];
    int t = threadIdx.x;
    if (t < 3) ok[t] = 1;
    __syncthreads();
    for (int i = t; i < 8192; i += 256) {
        unsigned v = m[i];
        if (!(v == 0u || v == 1u)) ok[0] = 0;
        if (!(v == 0u || v == 0x3F800000u)) ok[1] = 0;
        unsigned lo = v & 0xFFFFu, hi = v >> 16;
        if (!((lo == 0u || lo == 0x3F80u) && (hi == 0u || hi == 0x3F80u))) ok[2] = 0;
    }
    __syncthreads();
    if (t == 0) gEnc = ok[0] ? 0 : (ok[1] ? 1 : (ok[2] ? 2 : 3));
}

__global__ void k_convmask(const void* __restrict__ m) {
    int i = blockIdx.x * 256 + threadIdx.x;
    if (i >= NB * NS) return;
    int e = gEnc;
    unsigned char v;
    if (e == 0)      v = ((const int*)m)[i] != 0;
    else if (e == 1) v = ((const float*)m)[i] != 0.f;
    else if (e == 2) v = ((const unsigned short*)m)[i] != 0;
    else             v = ((const unsigned char*)m)[i] != 0;
    gValid[i] = v;
}

__global__ void k_len() {
    const int b = blockIdx.x;
    const int t = threadIdx.x;
    __shared__ int scnt[256], smax[256];
    int cnt = 0, mx = -1;
    for (int i = t; i < NS; i += 256)
        if (gValid[b * NS + i]) { cnt++; mx = i; }
    scnt[t] = cnt; smax[t] = mx;
    __syncthreads();
    for (int s = 128; s > 0; s >>= 1) {
        if (t < s) {
            scnt[t] += scnt[t + s];
            smax[t] = max(smax[t], smax[t + s]);
        }
        __syncthreads();
    }
    if (t == 0) {
        int len = scnt[0];
        gLen[b] = (len > 0 && smax[0] == len - 1) ? len : NS;
    }
}

__global__ void k_zero_l() {
    int i = blockIdx.x * 256 + threadIdx.x;
    if (i < NBH * NS) gL[i] = 0.f;
}
__global__ void k_linv() {
    int i = blockIdx.x * 256 + threadIdx.x;
    if (i < NBH * NS) gLinv[i] = 1.0f / gL[i];
}

// ---------------- fp32 -> bf16 conversion --------------------------------------------
__global__ void k_conv(const float* __restrict__ x, const float* __restrict__ w) {
    const size_t NX = (size_t)NB * NS * NE;
    const size_t NW = (size_t)2 * NE * NE;
    size_t i = ((size_t)blockIdx.x * 256 + threadIdx.x) * 4;
    if (i < NX) {
        float4 v = *(const float4*)(x + i);
        __nv_bfloat162* d = (__nv_bfloat162*)(gXb + i);
        d[0] = __floats2bfloat162_rn(v.x, v.y);
        d[1] = __floats2bfloat162_rn(v.z, v.w);
    } else {
        size_t j = i - NX;
        if (j < NW) {
            float4 v = *(const float4*)(w + j);
            __nv_bfloat162* d = (__nv_bfloat162*)(gWb + j);
            d[0] = __floats2bfloat162_rn(v.x, v.y);
            d[1] = __floats2bfloat162_rn(v.z, v.w);
        }
    }
}

// ---------------- GEMM1: Q/K projection ----------------------------------------------
__global__ void __launch_bounds__(128, 2) k_proj(const float* __restrict__ bias) {
    extern __shared__ char dsm[];
    const int bm = blockIdx.y * 128, bn = blockIdx.x * 128;
    float c[4][8][4] = {};
    gemm_core<32>(gXb + (size_t)bm * 1024, gWb + (size_t)bn * 1024, 1024, c, dsm);

    const int lane = threadIdx.x & 31, warp = threadIdx.x >> 5;
    const int wm = warp >> 1, wn = warp & 1;
    const int g = lane >> 2, t2 = (lane & 3) * 2;
    const int which = bn >> 10;                 // 0=Q, 1=K
    const int h = (bn >> 8) & 3;
    __nv_bfloat16* dst = which ? gK : gQ;
    const float sc = which ? 1.0f : 0.0625f;
#pragma unroll
    for (int mi = 0; mi < 4; mi++) {
#pragma unroll
        for (int half = 0; half < 2; half++) {
            int m = bm + wm * 64 + mi * 16 + g + half * 8;
            int b = m >> 11, s = m & 2047;
            __nv_bfloat16* drow = dst + ((size_t)(b * 4 + h) * NS + s) * ND;
#pragma unroll
            for (int ni = 0; ni < 8; ni++) {
                int n = bn + wn * 64 + ni * 8 + t2;
                float v0 = (c[mi][ni][half * 2 + 0] + bias[n]) * sc;
                float v1 = (c[mi][ni][half * 2 + 1] + bias[n + 1]) * sc;
                *(__nv_bfloat162*)(drow + (n & 255)) = __floats2bfloat162_rn(v0, v1);
            }
        }
    }
}

// ---------------- GEMM2: P = exp(Q K^T), mask, row sums ------------------------------
__global__ void __launch_bounds__(128, 2) k_scores() {
    extern __shared__ char dsm[];
    __shared__ float lrow[128];
    const int bh = blockIdx.z;
    const int bq = blockIdx.y * 128, bk = blockIdx.x * 128;
    const int bidx = bh >> 2;
    if (bk >= gLen[bidx]) return;               // fully-masked k-tile: skip
    lrow[threadIdx.x] = 0.f;

    float c[4][8][4] = {};
    const __nv_bfloat16* Qb = gQ + ((size_t)bh * NS + bq) * ND;
    const __nv_bfloat16* Kb = gK + ((size_t)bh * NS + bk) * ND;
    gemm_core<8>(Qb, Kb, ND, c, dsm);

    const int lane = threadIdx.x & 31, warp = threadIdx.x >> 5;
    const int wm = warp >> 1, wn = warp & 1;
    const int g = lane >> 2, t2 = (lane & 3) * 2;

    unsigned char vm[8][2];
#pragma unroll
    for (int ni = 0; ni < 8; ni++) {
        int kc = bk + wn * 64 + ni * 8 + t2;
        vm[ni][0] = gValid[bidx * NS + kc];
        vm[ni][1] = gValid[bidx * NS + kc + 1];
    }
#pragma unroll
    for (int mi = 0; mi < 4; mi++) {
#pragma unroll
        for (int half = 0; half < 2; half++) {
            int qrow = wm * 64 + mi * 16 + g + half * 8;
            __nv_bfloat16* prow = gP + ((size_t)bh * NS + bq + qrow) * NS + bk + wn * 64;
            float rs = 0.f;
#pragma unroll
            for (int ni = 0; ni < 8; ni++) {
                float p0 = vm[ni][0] ? __expf(c[mi][ni][half * 2 + 0]) : 0.f;
                float p1 = vm[ni][1] ? __expf(c[mi][ni][half * 2 + 1]) : 0.f;
                rs += p0 + p1;
                *(__nv_bfloat162*)(prow + ni * 8 + t2) = __floats2bfloat162_rn(p0, p1);
            }
            // reduce across the 4 lanes sharing this row, then one shared atomic
            rs += __shfl_xor_sync(0xFFFFFFFFu, rs, 1);
            rs += __shfl_xor_sync(0xFFFFFFFFu, rs, 2);
            if ((lane & 3) == 0) atomicAdd(&lrow[qrow], rs);
        }
    }
    __syncthreads();
    atomicAdd(&gL[bh * NS + bq + threadIdx.x], lrow[threadIdx.x]);
}

// ---------------- column sums over P (bf16x2 per thread) -------------------------------
// NOTE: shared loads are done by ALL threads before any per-thread culling
// (R5 bug: divergent cooperative load left ls[] partially uninitialized).
__global__ void __launch_bounds__(256) k_colsum() {
    const int bh = blockIdx.y;
    const int bidx = bh >> 2;
    const int len = gLen[bidx];
    const int lenR = (len + 127) & ~127;
    const int k = blockIdx.x * 512 + threadIdx.x * 2;
    __shared__ float ls[NS];
    for (int i = threadIdx.x; i < NS; i += 256) ls[i] = gLinv[bh * NS + i];
    __syncthreads();
    float2 out = {0.f, 0.f};
    if (k < lenR) {
        const __nv_bfloat16* Pc = gP + (size_t)bh * NS * NS + k;
        float a0 = 0, b0 = 0, a1 = 0, b1 = 0;
        for (int q = 0; q < NS; q += 2) {
            float2 v0 = __bfloat1622float2(*(const __nv_bfloat162*)(Pc + (size_t)q * NS));
            float2 v1 = __bfloat1622float2(*(const __nv_bfloat162*)(Pc + (size_t)(q + 1) * NS));
            a0 += v0.x * ls[q];     b0 += v0.y * ls[q];
            a1 += v1.x * ls[q + 1]; b1 += v1.y * ls[q + 1];
        }
        out.x = a0 + a1; out.y = b0 + b1;
    }
    gColsum[bh * NS + k] = out.x;
    gColsum[bh * NS + k + 1] = out.y;
}

__global__ void k_cs() {
    int i = blockIdx.x * 256 + threadIdx.x;
    if (i >= NB * NS) return;
    int b = i >> 11, q = i & 2047;
    float s = 0.f;
#pragma unroll
    for (int h = 0; h < NH; h++) s += gColsum[(b * NH + h) * NS + q];
    gCs[i] = 0.25f * s;
}

__global__ void __launch_bounds__(256) k_g() {
    const int bh = blockIdx.y;
    const int bidx = bh >> 2;
    const int len = gLen[bidx];
    const int lenR = (len + 127) & ~127;
    const int k = blockIdx.x * 512 + threadIdx.x * 2;
    __shared__ float ws[NS];
    for (int i = threadIdx.x; i < NS; i += 256)
        ws[i] = gCs[bidx * NS + i] * gLinv[bh * NS + i];
    __syncthreads();
    float2 out = {0.f, 0.f};
    if (k < lenR) {
        const __nv_bfloat16* Pc = gP + (size_t)bh * NS * NS + k;
        float a0 = 0, b0 = 0, a1 = 0, b1 = 0;
        for (int q = 0; q < NS; q += 2) {
            float2 v0 = __bfloat1622float2(*(const __nv_bfloat162*)(Pc + (size_t)q * NS));
            float2 v1 = __bfloat1622float2(*(const __nv_bfloat162*)(Pc + (size_t)(q + 1) * NS));
            a0 += v0.x * ws[q];     b0 += v0.y * ws[q];
            a1 += v1.x * ws[q + 1]; b1 += v1.y * ws[q + 1];
        }
        out.x = a0 + a1; out.y = b0 + b1;
    }
    gG[bh * NS + k] = out.x;
    gG[bh * NS + k + 1] = out.y;
}

// ---------------- u[bh,e] = sum_k g[bh,k] x[b,k,e] ------------------------------------
__global__ void __launch_bounds__(256) k_u(const float* __restrict__ x) {
    const int b = blockIdx.y;
    const int e = blockIdx.x * 256 + threadIdx.x;
    __shared__ float gs[4][NS];
    for (int i = threadIdx.x; i < 4 * NS; i += 256)
        gs[i >> 11][i & 2047] = gG[(b * 4 + (i >> 11)) * NS + (i & 2047)];
    __syncthreads();
    const int kend = (gLen[b] + 3) & ~3;
    float a0 = 0, a1 = 0, a2 = 0, a3 = 0;
    const float* xb = x + (size_t)b * NS * NE + e;
#pragma unroll 4
    for (int k = 0; k < kend; k++) {
        float xv = xb[(size_t)k * NE];
        a0 += gs[0][k] * xv; a1 += gs[1][k] * xv;
        a2 += gs[2][k] * xv; a3 += gs[3][k] * xv;
    }
    gU[(b * 4 + 0) * NE + e] = a0;
    gU[(b * 4 + 1) * NE + e] = a1;
    gU[(b * 4 + 2) * NE + e] = a2;
    gU[(b * 4 + 3) * NE + e] = a3;
}

__global__ void k_sg() {
    int bh = blockIdx.x;
    float s = 0.f;
    for (int k = threadIdx.x; k < NS; k += 256) s += gG[bh * NS + k];
    __shared__ float r[256];
    r[threadIdx.x] = s;
    __syncthreads();
    for (int st = 128; st > 0; st >>= 1) {
        if (threadIdx.x < st) r[threadIdx.x] += r[threadIdx.x + st];
        __syncthreads();
    }
    if (threadIdx.x == 0) gSg[bh] = r[0];
}

// ---------------- y = u @ Wv^T + sg*bv -------------------------------------------------
__global__ void __launch_bounds__(256) k_yv(const float* __restrict__ ipw,
                                            const float* __restrict__ ipb) {
    const int row = blockIdx.x;
    const int h = row >> 8;
    const int t = threadIdx.x;
    __shared__ float us[16 * 256];
    __shared__ float red[256];
    float acc[16];
#pragma unroll
    for (int b = 0; b < 16; b++) acc[b] = 0.f;
    for (int j0 = 0; j0 < NE; j0 += 256) {
        __syncthreads();
        for (int i = t; i < 16 * 256; i += 256) {
            int b = i >> 8, jj = i & 255;
            us[i] = gU[(b * 4 + h) * NE + j0 + jj];
        }
        __syncthreads();
        float wv = ipw[(size_t)(2 * NE + row) * NE + j0 + t];
#pragma unroll
        for (int b = 0; b < 16; b++) acc[b] += us[b * 256 + t] * wv;
    }
    float bv = ipb[2 * NE + row];
    for (int b = 0; b < 16; b++) {
        red[t] = acc[b];
        __syncthreads();
        for (int s = 128; s > 0; s >>= 1) {
            if (t < s) red[t] += red[t + s];
            __syncthreads();
        }
        if (t == 0) gY[b * NE + row] = red[0] + gSg[b * 4 + h] * bv;
        __syncthreads();
    }
}

// ---------------- out = y @ out_w^T + S*out_b ------------------------------------------
__global__ void __launch_bounds__(256) k_out(const float* __restrict__ out_w,
                                             const float* __restrict__ out_b,
                                             float* __restrict__ out) {
    const int e = blockIdx.x;
    const int t = threadIdx.x;
    __shared__ float ys[16 * 256];
    __shared__ float red[256];
    float acc[16];
#pragma unroll
    for (int b = 0; b < 16; b++) acc[b] = 0.f;
    for (int j0 = 0; j0 < NE; j0 += 256) {
        __syncthreads();
        for (int i = t; i < 16 * 256; i += 256) {
            int b = i >> 8, jj = i & 255;
            ys[i] = gY[b * NE + j0 + jj];
        }
        __syncthreads();
        float wv = out_w[(size_t)e * NE + j0 + t];
#pragma unroll
        for (int b = 0; b < 16; b++) acc[b] += ys[b * 256 + t] * wv;
    }
    for (int b = 0; b < 16; b++) {
        red[t] = acc[b];
        __syncthreads();
        for (int s = 128; s > 0; s >>= 1) {
            if (t < s) red[t] += red[t + s];
            __syncthreads();
        }
        if (t == 0) out[b * NE + e] = red[0] + 2048.0f * out_b[e];
        __syncthreads();
    }
}

// ---------------- launch ----------------------------------------------------------------
extern "C" void kernel_launch(void* const* d_in, const int* in_sizes, int n_in,
                              void* d_out, int out_size) {
    const float* x   = (const float*)d_in[0];
    const void*  msk = d_in[1];
    const float* ipw = (const float*)d_in[2];
    const float* ipb = (const float*)d_in[3];
    const float* ow  = (const float*)d_in[4];
    const float* ob  = (const float*)d_in[5];
    float* out = (float*)d_out;

    const int SMEM_GEMM = 4 * 16384;   // 64KB
    static bool attr_set = false;
    if (!attr_set) {
        cudaFuncSetAttribute(k_proj, cudaFuncAttributeMaxDynamicSharedMemorySize, SMEM_GEMM);
        cudaFuncSetAttribute(k_scores, cudaFuncAttributeMaxDynamicSharedMemorySize, SMEM_GEMM);
        attr_set = true;
    }

    k_zero_l<<<512, 256>>>();
    k_classify<<<1, 256>>>((const unsigned*)msk);
    k_convmask<<<128, 256>>>(msk);
    k_len<<<NB, 256>>>();

    k_conv<<<(int)(((size_t)NB * NS * NE + (size_t)2 * NE * NE) / 4 / 256), 256>>>(x, ipw);

    dim3 g1(16, 256);                   // N=2048/128, M=32768/128
    k_proj<<<g1, 128, SMEM_GEMM>>>(ipb);

    dim3 g2(16, 16, NBH);               // ktile, qtile, bh
    k_scores<<<g2, 128, SMEM_GEMM>>>();

    k_linv<<<512, 256>>>();

    dim3 g3(4, NBH);                    // 512 cols per block
    k_colsum<<<g3, 256>>>();
    k_cs<<<128, 256>>>();
    k_g<<<g3, 256>>>();

    dim3 g4(4, NB);
    k_u<<<g4, 256>>>(x);
    k_sg<<<NBH, 256>>>();
    k_yv<<<NE, 256>>>(ipw, ipb);
    k_out<<<NE, 256>>>(ow, ob, out);
}

// round 7
// speedup vs baseline: 1.0254x; 1.0254x over previous
#include <cuda_runtime.h>
#include <cuda_bf16.h>
#include <cstdint>

#define NB 16
#define NS 2048
#define NE 1024
#define NH 4
#define ND 256
#define NBH 64
#define BK 64
#define STG 32768   // bytes per pipeline stage: A 16KB + B 16KB

// ---------------- device scratch ------------------------------------------------
__device__ __align__(16) __nv_bfloat16 gXb[(size_t)NB * NS * NE];
__device__ __align__(16) __nv_bfloat16 gWb[(size_t)2 * NE * NE];
__device__ __align__(16) __nv_bfloat16 gQ[(size_t)NBH * NS * ND];   // scaled by 1/16
__device__ __align__(16) __nv_bfloat16 gK[(size_t)NBH * NS * ND];
__device__ __align__(16) __nv_bfloat16 gP[(size_t)NBH * NS * NS];   // exp(scores)
__device__ float gL[NBH * NS];
__device__ float gLinv[NBH * NS];
__device__ float gColsum[NBH * NS];
__device__ float gCs[NB * NS];
__device__ float gG[NBH * NS];
__device__ float gSg[NBH];
__device__ float gU[NBH * NE];
__device__ float gY[NB * NE];
__device__ unsigned char gValid[NB * NS];
__device__ int gLen[NB];
__device__ int gEnc;

// ---------------- helpers ---------------------------------------------------------
__device__ __forceinline__ void cpa16(uint32_t s, const void* g) {
    asm volatile("cp.async.cg.shared.global [%0], [%1], 16;\n" :: "r"(s), "l"(g));
}
__device__ __forceinline__ void cp_commit() { asm volatile("cp.async.commit_group;\n"); }
template <int N>
__device__ __forceinline__ void cp_wait() { asm volatile("cp.async.wait_group %0;\n" :: "n"(N)); }

__device__ __forceinline__ void ldm4(uint32_t (&r)[4], uint32_t addr) {
    asm volatile("ldmatrix.sync.aligned.m8n8.x4.shared.b16 {%0,%1,%2,%3}, [%4];"
                 : "=r"(r[0]), "=r"(r[1]), "=r"(r[2]), "=r"(r[3]) : "r"(addr));
}

__device__ __forceinline__ void mma16816(float (&d)[4], const uint32_t (&a)[4],
                                         uint32_t b0, uint32_t b1) {
    asm volatile("mma.sync.aligned.m16n8k16.row.col.f32.bf16.bf16.f32 "
                 "{%0,%1,%2,%3}, {%4,%5,%6,%7}, {%8,%9}, {%0,%1,%2,%3};"
                 : "+f"(d[0]), "+f"(d[1]), "+f"(d[2]), "+f"(d[3])
                 : "r"(a[0]), "r"(a[1]), "r"(a[2]), "r"(a[3]), "r"(b0), "r"(b1));
}

// 128B-row swizzle (rows of 64 bf16, 8 chunks of 16B): chunk' = c ^ (row & 7)
__device__ __forceinline__ uint32_t swz128(uint32_t row, uint32_t c16) {
    return row * 128u + ((c16 ^ (row & 7u)) << 4);
}

// one stage: A 128x64 bf16 (16KB) at +0, B 128x64 bf16 (16KB) at +16384; 256 threads
__device__ __forceinline__ void load_stage(uint32_t sbase,
                                           const __nv_bfloat16* __restrict__ Ag,
                                           const __nv_bfloat16* __restrict__ Bg,
                                           int lda, int tid) {
#pragma unroll
    for (int i = 0; i < 4; i++) {
        int ci = i * 256 + tid;
        uint32_t row = ci >> 3, c16 = ci & 7;
        cpa16(sbase + swz128(row, c16), Ag + (size_t)row * lda + c16 * 8);
        cpa16(sbase + 16384 + swz128(row, c16), Bg + (size_t)row * lda + c16 * 8);
    }
}

// 128x128 block, 256 threads = 8 warps (2x4), warp tile 64x32, BK=64, 3-stage.
template <int KIT>
__device__ __forceinline__ void gemm_core(const __nv_bfloat16* __restrict__ A,
                                          const __nv_bfloat16* __restrict__ B,
                                          int lda, float (&c)[4][4][4], char* dsm) {
    uint32_t s0;
    asm("{ .reg .u64 t; cvta.to.shared.u64 t, %1; cvt.u32.u64 %0, t; }" : "=r"(s0) : "l"(dsm));
    const int tid = threadIdx.x, lane = tid & 31, warp = tid >> 5;
    const int wm = warp >> 2, wn = warp & 3;

    load_stage(s0, A, B, lda, tid);
    cp_commit();
    if (1 < KIT) load_stage(s0 + STG, A + BK, B + BK, lda, tid);
    cp_commit();

    for (int kt = 0; kt < KIT; kt++) {
        cp_wait<1>();
        __syncthreads();
        if (kt + 2 < KIT)
            load_stage(s0 + ((kt + 2) % 3) * STG,
                       A + (size_t)(kt + 2) * BK, B + (size_t)(kt + 2) * BK, lda, tid);
        cp_commit();

        uint32_t aB = s0 + (kt % 3) * STG;
        uint32_t bB = aB + 16384;
#pragma unroll
        for (int ks = 0; ks < 4; ks++) {
            uint32_t c16 = ks * 2 + (lane >> 4);
            uint32_t a[4][4];
#pragma unroll
            for (int mi = 0; mi < 4; mi++)
                ldm4(a[mi], aB + swz128(wm * 64 + mi * 16 + (lane & 15), c16));
            uint32_t b[4][2];
#pragma unroll
            for (int p = 0; p < 2; p++) {
                uint32_t q[4];
                ldm4(q, bB + swz128(wn * 32 + p * 16 + (lane & 15), c16));
                b[p * 2 + 0][0] = q[0]; b[p * 2 + 0][1] = q[2];
                b[p * 2 + 1][0] = q[1]; b[p * 2 + 1][1] = q[3];
            }
#pragma unroll
            for (int mi = 0; mi < 4; mi++)
#pragma unroll
                for (int ni = 0; ni < 4; ni++)
                    mma16816(c[mi][ni], a[mi], b[ni][0], b[ni][1]);
        }
    }
}

// ---------------- mask handling -----------------------------------------------------
__global__ void k_classify(const unsigned* __restrict__ m) {
    __shared__ int ok[3];
    int t = threadIdx.x;
    if (t < 3) ok[t] = 1;
    __syncthreads();
    for (int i = t; i < 8192; i += 256) {
        unsigned v = m[i];
        if (!(v == 0u || v == 1u)) ok[0] = 0;
        if (!(v == 0u || v == 0x3F800000u)) ok[1] = 0;
        unsigned lo = v & 0xFFFFu, hi = v >> 16;
        if (!((lo == 0u || lo == 0x3F80u) && (hi == 0u || hi == 0x3F80u))) ok[2] = 0;
    }
    __syncthreads();
    if (t == 0) gEnc = ok[0] ? 0 : (ok[1] ? 1 : (ok[2] ? 2 : 3));
}

__global__ void k_convmask(const void* __restrict__ m) {
    int i = blockIdx.x * 256 + threadIdx.x;
    if (i >= NB * NS) return;
    int e = gEnc;
    unsigned char v;
    if (e == 0)      v = ((const int*)m)[i] != 0;
    else if (e == 1) v = ((const float*)m)[i] != 0.f;
    else if (e == 2) v = ((const unsigned short*)m)[i] != 0;
    else             v = ((const unsigned char*)m)[i] != 0;
    gValid[i] = v;
}

__global__ void k_len() {
    const int b = blockIdx.x;
    const int t = threadIdx.x;
    __shared__ int scnt[256], smax[256];
    int cnt = 0, mx = -1;
    for (int i = t; i < NS; i += 256)
        if (gValid[b * NS + i]) { cnt++; mx = i; }
    scnt[t] = cnt; smax[t] = mx;
    __syncthreads();
    for (int s = 128; s > 0; s >>= 1) {
        if (t < s) {
            scnt[t] += scnt[t + s];
            smax[t] = max(smax[t], smax[t + s]);
        }
        __syncthreads();
    }
    if (t == 0) {
        int len = scnt[0];
        gLen[b] = (len > 0 && smax[0] == len - 1) ? len : NS;
    }
}

__global__ void k_zero_l() {
    int i = blockIdx.x * 256 + threadIdx.x;
    if (i < NBH * NS) gL[i] = 0.f;
}
__global__ void k_linv() {
    int i = blockIdx.x * 256 + threadIdx.x;
    if (i < NBH * NS) gLinv[i] = 1.0f / gL[i];
}

// ---------------- fp32 -> bf16 conversion --------------------------------------------
__global__ void k_conv(const float* __restrict__ x, const float* __restrict__ w) {
    const size_t NX = (size_t)NB * NS * NE;
    const size_t NW = (size_t)2 * NE * NE;
    size_t i = ((size_t)blockIdx.x * 256 + threadIdx.x) * 4;
    if (i < NX) {
        float4 v = *(const float4*)(x + i);
        __nv_bfloat162* d = (__nv_bfloat162*)(gXb + i);
        d[0] = __floats2bfloat162_rn(v.x, v.y);
        d[1] = __floats2bfloat162_rn(v.z, v.w);
    } else {
        size_t j = i - NX;
        if (j < NW) {
            float4 v = *(const float4*)(w + j);
            __nv_bfloat162* d = (__nv_bfloat162*)(gWb + j);
            d[0] = __floats2bfloat162_rn(v.x, v.y);
            d[1] = __floats2bfloat162_rn(v.z, v.w);
        }
    }
}

// ---------------- GEMM1: Q/K projection ----------------------------------------------
__global__ void __launch_bounds__(256, 2) k_proj(const float* __restrict__ bias) {
    extern __shared__ char dsm[];
    const int bm = blockIdx.y * 128, bn = blockIdx.x * 128;
    const int which = bn >> 10;                 // 0=Q, 1=K
    const int bb = bm >> 11, ss = bm & 2047;
    // K rows for masked positions are never read (scores k-tiles culled /
    // epilogue masks): skip whole tile.
    if (which == 1 && ss >= gLen[bb]) return;

    float c[4][4][4] = {};
    gemm_core<16>(gXb + (size_t)bm * 1024, gWb + (size_t)bn * 1024, 1024, c, dsm);

    const int lane = threadIdx.x & 31, warp = threadIdx.x >> 5;
    const int wm = warp >> 2, wn = warp & 3;
    const int g = lane >> 2, t2 = (lane & 3) * 2;
    const int h = (bn >> 8) & 3;
    __nv_bfloat16* dst = which ? gK : gQ;
    const float sc = which ? 1.0f : 0.0625f;    // fold 1/sqrt(256) into Q
#pragma unroll
    for (int mi = 0; mi < 4; mi++) {
#pragma unroll
        for (int half = 0; half < 2; half++) {
            int m = bm + wm * 64 + mi * 16 + g + half * 8;
            int b = m >> 11, s = m & 2047;
            __nv_bfloat16* drow = dst + ((size_t)(b * 4 + h) * NS + s) * ND;
#pragma unroll
            for (int ni = 0; ni < 4; ni++) {
                int n = bn + wn * 32 + ni * 8 + t2;
                float v0 = (c[mi][ni][half * 2 + 0] + bias[n]) * sc;
                float v1 = (c[mi][ni][half * 2 + 1] + bias[n + 1]) * sc;
                *(__nv_bfloat162*)(drow + (n & 255)) = __floats2bfloat162_rn(v0, v1);
            }
        }
    }
}

// ---------------- GEMM2: P = exp(Q K^T), mask, row sums ------------------------------
__global__ void __launch_bounds__(256, 2) k_scores() {
    extern __shared__ char dsm[];
    __shared__ float lrow[128];
    const int bh = blockIdx.z;
    const int bq = blockIdx.y * 128, bk = blockIdx.x * 128;
    const int bidx = bh >> 2;
    if (bk >= gLen[bidx]) return;               // fully-masked k-tile: skip
    if (threadIdx.x < 128) lrow[threadIdx.x] = 0.f;

    float c[4][4][4] = {};
    const __nv_bfloat16* Qb = gQ + ((size_t)bh * NS + bq) * ND;
    const __nv_bfloat16* Kb = gK + ((size_t)bh * NS + bk) * ND;
    gemm_core<4>(Qb, Kb, ND, c, dsm);

    const int lane = threadIdx.x & 31, warp = threadIdx.x >> 5;
    const int wm = warp >> 2, wn = warp & 3;
    const int g = lane >> 2, t2 = (lane & 3) * 2;

    unsigned char vm[4][2];
#pragma unroll
    for (int ni = 0; ni < 4; ni++) {
        int kc = bk + wn * 32 + ni * 8 + t2;
        vm[ni][0] = gValid[bidx * NS + kc];
        vm[ni][1] = gValid[bidx * NS + kc + 1];
    }
#pragma unroll
    for (int mi = 0; mi < 4; mi++) {
#pragma unroll
        for (int half = 0; half < 2; half++) {
            int qrow = wm * 64 + mi * 16 + g + half * 8;
            __nv_bfloat16* prow = gP + ((size_t)bh * NS + bq + qrow) * NS + bk + wn * 32;
            float rs = 0.f;
#pragma unroll
            for (int ni = 0; ni < 4; ni++) {
                float p0 = vm[ni][0] ? __expf(c[mi][ni][half * 2 + 0]) : 0.f;
                float p1 = vm[ni][1] ? __expf(c[mi][ni][half * 2 + 1]) : 0.f;
                rs += p0 + p1;
                *(__nv_bfloat162*)(prow + ni * 8 + t2) = __floats2bfloat162_rn(p0, p1);
            }
            rs += __shfl_xor_sync(0xFFFFFFFFu, rs, 1);
            rs += __shfl_xor_sync(0xFFFFFFFFu, rs, 2);
            if ((lane & 3) == 0) atomicAdd(&lrow[qrow], rs);
        }
    }
    __syncthreads();
    if (threadIdx.x < 128) atomicAdd(&gL[bh * NS + bq + threadIdx.x], lrow[threadIdx.x]);
}

// ---------------- column sums over P (bf16x2 per thread) -------------------------------
__global__ void __launch_bounds__(256) k_colsum() {
    const int bh = blockIdx.y;
    const int bidx = bh >> 2;
    const int len = gLen[bidx];
    const int lenR = (len + 127) & ~127;
    const int k = blockIdx.x * 512 + threadIdx.x * 2;
    __shared__ float ls[NS];
    for (int i = threadIdx.x; i < NS; i += 256) ls[i] = gLinv[bh * NS + i];
    __syncthreads();
    float2 out = {0.f, 0.f};
    if (k < lenR) {
        const __nv_bfloat16* Pc = gP + (size_t)bh * NS * NS + k;
        float a0 = 0, b0 = 0, a1 = 0, b1 = 0;
        for (int q = 0; q < NS; q += 2) {
            float2 v0 = __bfloat1622float2(*(const __nv_bfloat162*)(Pc + (size_t)q * NS));
            float2 v1 = __bfloat1622float2(*(const __nv_bfloat162*)(Pc + (size_t)(q + 1) * NS));
            a0 += v0.x * ls[q];     b0 += v0.y * ls[q];
            a1 += v1.x * ls[q + 1]; b1 += v1.y * ls[q + 1];
        }
        out.x = a0 + a1; out.y = b0 + b1;
    }
    gColsum[bh * NS + k] = out.x;
    gColsum[bh * NS + k + 1] = out.y;
}

__global__ void k_cs() {
    int i = blockIdx.x * 256 + threadIdx.x;
    if (i >= NB * NS) return;
    int b = i >> 11, q = i & 2047;
    float s = 0.f;
#pragma unroll
    for (int h = 0; h < NH; h++) s += gColsum[(b * NH + h) * NS + q];
    gCs[i] = 0.25f * s;
}

__global__ void __launch_bounds__(256) k_g() {
    const int bh = blockIdx.y;
    const int bidx = bh >> 2;
    const int len = gLen[bidx];
    const int lenR = (len + 127) & ~127;
    const int k = blockIdx.x * 512 + threadIdx.x * 2;
    __shared__ float ws[NS];
    for (int i = threadIdx.x; i < NS; i += 256)
        ws[i] = gCs[bidx * NS + i] * gLinv[bh * NS + i];
    __syncthreads();
    float2 out = {0.f, 0.f};
    if (k < lenR) {
        const __nv_bfloat16* Pc = gP + (size_t)bh * NS * NS + k;
        float a0 = 0, b0 = 0, a1 = 0, b1 = 0;
        for (int q = 0; q < NS; q += 2) {
            float2 v0 = __bfloat1622float2(*(const __nv_bfloat162*)(Pc + (size_t)q * NS));
            float2 v1 = __bfloat1622float2(*(const __nv_bfloat162*)(Pc + (size_t)(q + 1) * NS));
            a0 += v0.x * ws[q];     b0 += v0.y * ws[q];
            a1 += v1.x * ws[q + 1]; b1 += v1.y * ws[q + 1];
        }
        out.x = a0 + a1; out.y = b0 + b1;
    }
    gG[bh * NS + k] = out.x;
    gG[bh * NS + k + 1] = out.y;
}

// ---------------- u[bh,e] = sum_k g[bh,k] x[b,k,e] ------------------------------------
__global__ void __launch_bounds__(256) k_u(const float* __restrict__ x) {
    const int b = blockIdx.y;
    const int e = blockIdx.x * 256 + threadIdx.x;
    __shared__ float gs[4][NS];
    for (int i = threadIdx.x; i < 4 * NS; i += 256)
        gs[i >> 11][i & 2047] = gG[(b * 4 + (i >> 11)) * NS + (i & 2047)];
    __syncthreads();
    const int kend = (gLen[b] + 3) & ~3;
    float a0 = 0, a1 = 0, a2 = 0, a3 = 0;
    const float* xb = x + (size_t)b * NS * NE + e;
#pragma unroll 4
    for (int k = 0; k < kend; k++) {
        float xv = xb[(size_t)k * NE];
        a0 += gs[0][k] * xv; a1 += gs[1][k] * xv;
        a2 += gs[2][k] * xv; a3 += gs[3][k] * xv;
    }
    gU[(b * 4 + 0) * NE + e] = a0;
    gU[(b * 4 + 1) * NE + e] = a1;
    gU[(b * 4 + 2) * NE + e] = a2;
    gU[(b * 4 + 3) * NE + e] = a3;
}

__global__ void k_sg() {
    int bh = blockIdx.x;
    float s = 0.f;
    for (int k = threadIdx.x; k < NS; k += 256) s += gG[bh * NS + k];
    __shared__ float r[256];
    r[threadIdx.x] = s;
    __syncthreads();
    for (int st = 128; st > 0; st >>= 1) {
        if (threadIdx.x < st) r[threadIdx.x] += r[threadIdx.x + st];
        __syncthreads();
    }
    if (threadIdx.x == 0) gSg[bh] = r[0];
}

// ---------------- y = u @ Wv^T + sg*bv -------------------------------------------------
__global__ void __launch_bounds__(256) k_yv(const float* __restrict__ ipw,
                                            const float* __restrict__ ipb) {
    const int row = blockIdx.x;
    const int h = row >> 8;
    const int t = threadIdx.x;
    __shared__ float us[16 * 256];
    __shared__ float red[256];
    float acc[16];
#pragma unroll
    for (int b = 0; b < 16; b++) acc[b] = 0.f;
    for (int j0 = 0; j0 < NE; j0 += 256) {
        __syncthreads();
        for (int i = t; i < 16 * 256; i += 256) {
            int b = i >> 8, jj = i & 255;
            us[i] = gU[(b * 4 + h) * NE + j0 + jj];
        }
        __syncthreads();
        float wv = ipw[(size_t)(2 * NE + row) * NE + j0 + t];
#pragma unroll
        for (int b = 0; b < 16; b++) acc[b] += us[b * 256 + t] * wv;
    }
    float bv = ipb[2 * NE + row];
    for (int b = 0; b < 16; b++) {
        red[t] = acc[b];
        __syncthreads();
        for (int s = 128; s > 0; s >>= 1) {
            if (t < s) red[t] += red[t + s];
            __syncthreads();
        }
        if (t == 0) gY[b * NE + row] = red[0] + gSg[b * 4 + h] * bv;
        __syncthreads();
    }
}

// ---------------- out = y @ out_w^T + S*out_b ------------------------------------------
__global__ void __launch_bounds__(256) k_out(const float* __restrict__ out_w,
                                             const float* __restrict__ out_b,
                                             float* __restrict__ out) {
    const int e = blockIdx.x;
    const int t = threadIdx.x;
    __shared__ float ys[16 * 256];
    __shared__ float red[256];
    float acc[16];
#pragma unroll
    for (int b = 0; b < 16; b++) acc[b] = 0.f;
    for (int j0 = 0; j0 < NE; j0 += 256) {
        __syncthreads();
        for (int i = t; i < 16 * 256; i += 256) {
            int b = i >> 8, jj = i & 255;
            ys[i] = gY[b * NE + j0 + jj];
        }
        __syncthreads();
        float wv = out_w[(size_t)e * NE + j0 + t];
#pragma unroll
        for (int b = 0; b < 16; b++) acc[b] += ys[b * 256 + t] * wv;
    }
    for (int b = 0; b < 16; b++) {
        red[t] = acc[b];
        __syncthreads();
        for (int s = 128; s > 0; s >>= 1) {
            if (t < s) red[t] += red[t + s];
            __syncthreads();
        }
        if (t == 0) out[b * NE + e] = red[0] + 2048.0f * out_b[e];
        __syncthreads();
    }
}

// ---------------- launch ----------------------------------------------------------------
extern "C" void kernel_launch(void* const* d_in, const int* in_sizes, int n_in,
                              void* d_out, int out_size) {
    const float* x   = (const float*)d_in[0];
    const void*  msk = d_in[1];
    const float* ipw = (const float*)d_in[2];
    const float* ipb = (const float*)d_in[3];
    const float* ow  = (const float*)d_in[4];
    const float* ob  = (const float*)d_in[5];
    float* out = (float*)d_out;

    const int SMEM_GEMM = 3 * STG;      // 96KB
    static bool attr_set = false;
    if (!attr_set) {
        cudaFuncSetAttribute(k_proj, cudaFuncAttributeMaxDynamicSharedMemorySize, SMEM_GEMM);
        cudaFuncSetAttribute(k_scores, cudaFuncAttributeMaxDynamicSharedMemorySize, SMEM_GEMM);
        attr_set = true;
    }

    k_zero_l<<<512, 256>>>();
    k_classify<<<1, 256>>>((const unsigned*)msk);
    k_convmask<<<128, 256>>>(msk);
    k_len<<<NB, 256>>>();

    k_conv<<<(int)(((size_t)NB * NS * NE + (size_t)2 * NE * NE) / 4 / 256), 256>>>(x, ipw);

    dim3 g1(16, 256);                   // N=2048/128, M=32768/128
    k_proj<<<g1, 256, SMEM_GEMM>>>(ipb);

    dim3 g2(16, 16, NBH);               // ktile, qtile, bh
    k_scores<<<g2, 256, SMEM_GEMM>>>();

    k_linv<<<512, 256>>>();

    dim3 g3(4, NBH);                    // 512 cols per block
    k_colsum<<<g3, 256>>>();
    k_cs<<<128, 256>>>();
    k_g<<<g3, 256>>>();

    dim3 g4(4, NB);
    k_u<<<g4, 256>>>(x);
    k_sg<<<NBH, 256>>>();
    k_yv<<<NE, 256>>>(ipw, ipb);
    k_out<<<NE, 256>>>(ow, ob, out);
}

// round 10
// speedup vs baseline: 1.0369x; 1.0112x over previous
#include <cuda_runtime.h>
#include <cuda_bf16.h>
#include <cstdint>

#define NB 16
#define NS 2048
#define NE 1024
#define NH 4
#define ND 256
#define NBH 64
#define BK 32

// ---------------- device scratch ------------------------------------------------
__device__ __align__(16) __nv_bfloat16 gXb[(size_t)NB * NS * NE];
__device__ __align__(16) __nv_bfloat16 gWb[(size_t)2 * NE * NE];
__device__ __align__(16) __nv_bfloat16 gQ[(size_t)NBH * NS * ND];   // scaled by 1/16
__device__ __align__(16) __nv_bfloat16 gK[(size_t)NBH * NS * ND];
__device__ __align__(16) __nv_bfloat16 gP[(size_t)NBH * NS * NS];   // exp(scores)
__device__ float gL[NBH * NS];
__device__ float gLinv[NBH * NS];
__device__ float gColsum[NBH * NS];
__device__ float gCs[NB * NS];
__device__ float gG[NBH * NS];
__device__ float gSg[NBH];
__device__ float gU[NBH * NE];
__device__ float gY[NB * NE];
__device__ unsigned char gValid[NB * NS];
__device__ int gLen[NB];
__device__ int gEnc;

// ---------------- helpers ---------------------------------------------------------
__device__ __forceinline__ void cpa16(uint32_t s, const void* g) {
    asm volatile("cp.async.cg.shared.global [%0], [%1], 16;\n" :: "r"(s), "l"(g));
}
__device__ __forceinline__ void cp_commit() { asm volatile("cp.async.commit_group;\n"); }
template <int N>
__device__ __forceinline__ void cp_wait() { asm volatile("cp.async.wait_group %0;\n" :: "n"(N)); }

__device__ __forceinline__ void ldm4(uint32_t (&r)[4], uint32_t addr) {
    asm volatile("ldmatrix.sync.aligned.m8n8.x4.shared.b16 {%0,%1,%2,%3}, [%4];"
                 : "=r"(r[0]), "=r"(r[1]), "=r"(r[2]), "=r"(r[3]) : "r"(addr));
}

__device__ __forceinline__ void mma16816(float (&d)[4], const uint32_t (&a)[4],
                                         uint32_t b0, uint32_t b1) {
    asm volatile("mma.sync.aligned.m16n8k16.row.col.f32.bf16.bf16.f32 "
                 "{%0,%1,%2,%3}, {%4,%5,%6,%7}, {%8,%9}, {%0,%1,%2,%3};"
                 : "+f"(d[0]), "+f"(d[1]), "+f"(d[2]), "+f"(d[3])
                 : "r"(a[0]), "r"(a[1]), "r"(a[2]), "r"(a[3]), "r"(b0), "r"(b1));
}

// 64B-row swizzle: rows of 32 bf16, 4 chunks of 16B. chunk' = c ^ ((row>>1)&3)
__device__ __forceinline__ uint32_t swz64(uint32_t row, uint32_t c16) {
    return row * 64u + ((c16 ^ ((row >> 1) & 3u)) << 4);
}

// one pipeline stage: A 128x32 bf16 (8KB) + B 128x32 bf16 (8KB), 256 threads
__device__ __forceinline__ void load_stage(uint32_t sA, uint32_t sB,
                                           const __nv_bfloat16* __restrict__ Ag,
                                           const __nv_bfloat16* __restrict__ Bg,
                                           int lda, int tid) {
#pragma unroll
    for (int i = 0; i < 2; i++) {
        int ci = i * 256 + tid;
        uint32_t row = ci >> 2, c16 = ci & 3;
        cpa16(sA + swz64(row, c16), Ag + (size_t)row * lda + c16 * 8);
        cpa16(sB + swz64(row, c16), Bg + (size_t)row * lda + c16 * 8);
    }
}

// 128x128 block, 256 threads = 8 warps (2x4), warp tile 64x32, 4-stage pipeline.
// (Exact R4 core — run-validated. 5-stage variant showed nondeterministic
// corruption in R8/R9 and is abandoned.)
template <int KIT>
__device__ __forceinline__ void gemm_core(const __nv_bfloat16* __restrict__ A,
                                          const __nv_bfloat16* __restrict__ B,
                                          int lda, float (&c)[4][4][4], char* dsm) {
    uint32_t s0;
    asm("{ .reg .u64 t; cvta.to.shared.u64 t, %1; cvt.u32.u64 %0, t; }" : "=r"(s0) : "l"(dsm));
    const int tid = threadIdx.x, lane = tid & 31, warp = tid >> 5;
    const int wm = warp >> 2, wn = warp & 3;

#pragma unroll
    for (int s = 0; s < 3; s++) {
        if (s < KIT)
            load_stage(s0 + s * 16384, s0 + s * 16384 + 8192,
                       A + s * BK, B + s * BK, lda, tid);
        cp_commit();
    }

    for (int kt = 0; kt < KIT; kt++) {
        cp_wait<2>();
        __syncthreads();
        if (kt + 3 < KIT)
            load_stage(s0 + ((kt + 3) & 3) * 16384, s0 + ((kt + 3) & 3) * 16384 + 8192,
                       A + (size_t)(kt + 3) * BK, B + (size_t)(kt + 3) * BK, lda, tid);
        cp_commit();

        uint32_t aB = s0 + (kt & 3) * 16384;
        uint32_t bB = aB + 8192;
#pragma unroll
        for (int ks = 0; ks < 2; ks++) {
            uint32_t c16 = ks * 2 + (lane >> 4);
            uint32_t a[4][4];
#pragma unroll
            for (int mi = 0; mi < 4; mi++)
                ldm4(a[mi], aB + swz64(wm * 64 + mi * 16 + (lane & 15), c16));
            uint32_t b[4][2];
#pragma unroll
            for (int p = 0; p < 2; p++) {
                uint32_t q[4];
                ldm4(q, bB + swz64(wn * 32 + p * 16 + (lane & 15), c16));
                b[p * 2 + 0][0] = q[0]; b[p * 2 + 0][1] = q[2];
                b[p * 2 + 1][0] = q[1]; b[p * 2 + 1][1] = q[3];
            }
#pragma unroll
            for (int mi = 0; mi < 4; mi++)
#pragma unroll
                for (int ni = 0; ni < 4; ni++)
                    mma16816(c[mi][ni], a[mi], b[ni][0], b[ni][1]);
        }
    }
}

// ---------------- mask handling -----------------------------------------------------
__global__ void k_classify(const unsigned* __restrict__ m) {
    __shared__ int ok[3];
    int t = threadIdx.x;
    if (t < 3) ok[t] = 1;
    __syncthreads();
    for (int i = t; i < 8192; i += 256) {
        unsigned v = m[i];
        if (!(v == 0u || v == 1u)) ok[0] = 0;
        if (!(v == 0u || v == 0x3F800000u)) ok[1] = 0;
        unsigned lo = v & 0xFFFFu, hi = v >> 16;
        if (!((lo == 0u || lo == 0x3F80u) && (hi == 0u || hi == 0x3F80u))) ok[2] = 0;
    }
    __syncthreads();
    if (t == 0) gEnc = ok[0] ? 0 : (ok[1] ? 1 : (ok[2] ? 2 : 3));
}

__global__ void k_convmask(const void* __restrict__ m) {
    int i = blockIdx.x * 256 + threadIdx.x;
    if (i >= NB * NS) return;
    int e = gEnc;
    unsigned char v;
    if (e == 0)      v = ((const int*)m)[i] != 0;
    else if (e == 1) v = ((const float*)m)[i] != 0.f;
    else if (e == 2) v = ((const unsigned short*)m)[i] != 0;
    else             v = ((const unsigned char*)m)[i] != 0;
    gValid[i] = v;
}

__global__ void k_len() {
    const int b = blockIdx.x;
    const int t = threadIdx.x;
    __shared__ int scnt[256], smax[256];
    int cnt = 0, mx = -1;
    for (int i = t; i < NS; i += 256)
        if (gValid[b * NS + i]) { cnt++; mx = i; }
    scnt[t] = cnt; smax[t] = mx;
    __syncthreads();
    for (int s = 128; s > 0; s >>= 1) {
        if (t < s) {
            scnt[t] += scnt[t + s];
            smax[t] = max(smax[t], smax[t + s]);
        }
        __syncthreads();
    }
    if (t == 0) {
        int len = scnt[0];
        gLen[b] = (len > 0 && smax[0] == len - 1) ? len : NS;
    }
}

__global__ void k_zero_l() {
    int i = blockIdx.x * 256 + threadIdx.x;
    if (i < NBH * NS) gL[i] = 0.f;
}
__global__ void k_linv() {
    int i = blockIdx.x * 256 + threadIdx.x;
    if (i < NBH * NS) gLinv[i] = 1.0f / gL[i];
}

// ---------------- fp32 -> bf16 conversion --------------------------------------------
__global__ void k_conv(const float* __restrict__ x, const float* __restrict__ w) {
    const size_t NX = (size_t)NB * NS * NE;
    const size_t NW = (size_t)2 * NE * NE;
    size_t i = ((size_t)blockIdx.x * 256 + threadIdx.x) * 4;
    if (i < NX) {
        float4 v = *(const float4*)(x + i);
        __nv_bfloat162* d = (__nv_bfloat162*)(gXb + i);
        d[0] = __floats2bfloat162_rn(v.x, v.y);
        d[1] = __floats2bfloat162_rn(v.z, v.w);
    } else {
        size_t j = i - NX;
        if (j < NW) {
            float4 v = *(const float4*)(w + j);
            __nv_bfloat162* d = (__nv_bfloat162*)(gWb + j);
            d[0] = __floats2bfloat162_rn(v.x, v.y);
            d[1] = __floats2bfloat162_rn(v.z, v.w);
        }
    }
}

// ---------------- GEMM1: Q/K projection ----------------------------------------------
__global__ void __launch_bounds__(256, 2) k_proj(const float* __restrict__ bias) {
    extern __shared__ char dsm[];
    const int bm = blockIdx.y * 128, bn = blockIdx.x * 128;
    const int which = bn >> 10;                 // 0=Q, 1=K
    const int bb = bm >> 11, ss = bm & 2047;
    // K rows for masked positions are never read: skip whole tile.
    if (which == 1 && ss >= gLen[bb]) return;

    float c[4][4][4] = {};
    gemm_core<32>(gXb + (size_t)bm * 1024, gWb + (size_t)bn * 1024, 1024, c, dsm);

    const int lane = threadIdx.x & 31, warp = threadIdx.x >> 5;
    const int wm = warp >> 2, wn = warp & 3;
    const int g = lane >> 2, t2 = (lane & 3) * 2;
    const int h = (bn >> 8) & 3;
    __nv_bfloat16* dst = which ? gK : gQ;
    const float sc = which ? 1.0f : 0.0625f;    // fold 1/sqrt(256) into Q
#pragma unroll
    for (int mi = 0; mi < 4; mi++) {
#pragma unroll
        for (int half = 0; half < 2; half++) {
            int m = bm + wm * 64 + mi * 16 + g + half * 8;
            int b = m >> 11, s = m & 2047;
            __nv_bfloat16* drow = dst + ((size_t)(b * 4 + h) * NS + s) * ND;
#pragma unroll
            for (int ni = 0; ni < 4; ni++) {
                int n = bn + wn * 32 + ni * 8 + t2;
                float v0 = (c[mi][ni][half * 2 + 0] + bias[n]) * sc;
                float v1 = (c[mi][ni][half * 2 + 1] + bias[n + 1]) * sc;
                *(__nv_bfloat162*)(drow + (n & 255)) = __floats2bfloat162_rn(v0, v1);
            }
        }
    }
}

// ---------------- GEMM2: P = exp(Q K^T), mask, row sums ------------------------------
__global__ void __launch_bounds__(256, 2) k_scores() {
    extern __shared__ char dsm[];
    __shared__ float lrow[128];
    const int bh = blockIdx.z;
    const int bq = blockIdx.y * 128, bk = blockIdx.x * 128;
    const int bidx = bh >> 2;
    if (bk >= gLen[bidx]) return;               // fully-masked k-tile: skip
    if (threadIdx.x < 128) lrow[threadIdx.x] = 0.f;

    float c[4][4][4] = {};
    const __nv_bfloat16* Qb = gQ + ((size_t)bh * NS + bq) * ND;
    const __nv_bfloat16* Kb = gK + ((size_t)bh * NS + bk) * ND;
    gemm_core<8>(Qb, Kb, ND, c, dsm);

    const int lane = threadIdx.x & 31, warp = threadIdx.x >> 5;
    const int wm = warp >> 2, wn = warp & 3;
    const int g = lane >> 2, t2 = (lane & 3) * 2;

    unsigned char vm[4][2];
#pragma unroll
    for (int ni = 0; ni < 4; ni++) {
        int kc = bk + wn * 32 + ni * 8 + t2;
        vm[ni][0] = gValid[bidx * NS + kc];
        vm[ni][1] = gValid[bidx * NS + kc + 1];
    }
#pragma unroll
    for (int mi = 0; mi < 4; mi++) {
#pragma unroll
        for (int half = 0; half < 2; half++) {
            int qrow = wm * 64 + mi * 16 + g + half * 8;
            __nv_bfloat16* prow = gP + ((size_t)bh * NS + bq + qrow) * NS + bk + wn * 32;
            float rs = 0.f;
#pragma unroll
            for (int ni = 0; ni < 4; ni++) {
                float p0 = vm[ni][0] ? __expf(c[mi][ni][half * 2 + 0]) : 0.f;
                float p1 = vm[ni][1] ? __expf(c[mi][ni][half * 2 + 1]) : 0.f;
                rs += p0 + p1;
                *(__nv_bfloat162*)(prow + ni * 8 + t2) = __floats2bfloat162_rn(p0, p1);
            }
            rs += __shfl_xor_sync(0xFFFFFFFFu, rs, 1);
            rs += __shfl_xor_sync(0xFFFFFFFFu, rs, 2);
            if ((lane & 3) == 0) atomicAdd(&lrow[qrow], rs);
        }
    }
    __syncthreads();
    if (threadIdx.x < 128) atomicAdd(&gL[bh * NS + bq + threadIdx.x], lrow[threadIdx.x]);
}

// ---------------- column sums over P (bf16x2 per thread) -------------------------------
__global__ void __launch_bounds__(256) k_colsum() {
    const int bh = blockIdx.y;
    const int bidx = bh >> 2;
    const int len = gLen[bidx];
    const int lenR = (len + 127) & ~127;
    const int k = blockIdx.x * 512 + threadIdx.x * 2;
    __shared__ float ls[NS];
    for (int i = threadIdx.x; i < NS; i += 256) ls[i] = gLinv[bh * NS + i];
    __syncthreads();
    float2 out = {0.f, 0.f};
    if (k < lenR) {
        const __nv_bfloat16* Pc = gP + (size_t)bh * NS * NS + k;
        float a0 = 0, b0 = 0, a1 = 0, b1 = 0;
        for (int q = 0; q < NS; q += 2) {
            float2 v0 = __bfloat1622float2(*(const __nv_bfloat162*)(Pc + (size_t)q * NS));
            float2 v1 = __bfloat1622float2(*(const __nv_bfloat162*)(Pc + (size_t)(q + 1) * NS));
            a0 += v0.x * ls[q];     b0 += v0.y * ls[q];
            a1 += v1.x * ls[q + 1]; b1 += v1.y * ls[q + 1];
        }
        out.x = a0 + a1; out.y = b0 + b1;
    }
    gColsum[bh * NS + k] = out.x;
    gColsum[bh * NS + k + 1] = out.y;
}

__global__ void k_cs() {
    int i = blockIdx.x * 256 + threadIdx.x;
    if (i >= NB * NS) return;
    int b = i >> 11, q = i & 2047;
    float s = 0.f;
#pragma unroll
    for (int h = 0; h < NH; h++) s += gColsum[(b * NH + h) * NS + q];
    gCs[i] = 0.25f * s;
}

__global__ void __launch_bounds__(256) k_g() {
    const int bh = blockIdx.y;
    const int bidx = bh >> 2;
    const int len = gLen[bidx];
    const int lenR = (len + 127) & ~127;
    const int k = blockIdx.x * 512 + threadIdx.x * 2;
    __shared__ float ws[NS];
    for (int i = threadIdx.x; i < NS; i += 256)
        ws[i] = gCs[bidx * NS + i] * gLinv[bh * NS + i];
    __syncthreads();
    float2 out = {0.f, 0.f};
    if (k < lenR) {
        const __nv_bfloat16* Pc = gP + (size_t)bh * NS * NS + k;
        float a0 = 0, b0 = 0, a1 = 0, b1 = 0;
        for (int q = 0; q < NS; q += 2) {
            float2 v0 = __bfloat1622float2(*(const __nv_bfloat162*)(Pc + (size_t)q * NS));
            float2 v1 = __bfloat1622float2(*(const __nv_bfloat162*)(Pc + (size_t)(q + 1) * NS));
            a0 += v0.x * ws[q];     b0 += v0.y * ws[q];
            a1 += v1.x * ws[q + 1]; b1 += v1.y * ws[q + 1];
        }
        out.x = a0 + a1; out.y = b0 + b1;
    }
    gG[bh * NS + k] = out.x;
    gG[bh * NS + k + 1] = out.y;
}

// ---------------- u[bh,e] = sum_k g[bh,k] x[b,k,e]  (fp32 x: precision-critical) ------
__global__ void __launch_bounds__(256) k_u(const float* __restrict__ x) {
    const int b = blockIdx.y;
    const int e = blockIdx.x * 256 + threadIdx.x;
    __shared__ float gs[4][NS];
    for (int i = threadIdx.x; i < 4 * NS; i += 256)
        gs[i >> 11][i & 2047] = gG[(b * 4 + (i >> 11)) * NS + (i & 2047)];
    __syncthreads();
    const int kend = (gLen[b] + 3) & ~3;
    float a0 = 0, a1 = 0, a2 = 0, a3 = 0;
    const float* xb = x + (size_t)b * NS * NE + e;
#pragma unroll 4
    for (int k = 0; k < kend; k++) {
        float xv = xb[(size_t)k * NE];
        a0 += gs[0][k] * xv; a1 += gs[1][k] * xv;
        a2 += gs[2][k] * xv; a3 += gs[3][k] * xv;
    }
    gU[(b * 4 + 0) * NE + e] = a0;
    gU[(b * 4 + 1) * NE + e] = a1;
    gU[(b * 4 + 2) * NE + e] = a2;
    gU[(b * 4 + 3) * NE + e] = a3;
}

__global__ void k_sg() {
    int bh = blockIdx.x;
    float s = 0.f;
    for (int k = threadIdx.x; k < NS; k += 256) s += gG[bh * NS + k];
    __shared__ float r[256];
    r[threadIdx.x] = s;
    __syncthreads();
    for (int st = 128; st > 0; st >>= 1) {
        if (threadIdx.x < st) r[threadIdx.x] += r[threadIdx.x + st];
        __syncthreads();
    }
    if (threadIdx.x == 0) gSg[bh] = r[0];
}

// ---------------- y = u @ Wv^T + sg*bv -------------------------------------------------
__global__ void __launch_bounds__(256) k_yv(const float* __restrict__ ipw,
                                            const float* __restrict__ ipb) {
    const int row = blockIdx.x;
    const int h = row >> 8;
    const int t = threadIdx.x;
    __shared__ float us[16 * 256];
    __shared__ float red[256];
    float acc[16];
#pragma unroll
    for (int b = 0; b < 16; b++) acc[b] = 0.f;
    for (int j0 = 0; j0 < NE; j0 += 256) {
        __syncthreads();
        for (int i = t; i < 16 * 256; i += 256) {
            int b = i >> 8, jj = i & 255;
            us[i] = gU[(b * 4 + h) * NE + j0 + jj];
        }
        __syncthreads();
        float wv = ipw[(size_t)(2 * NE + row) * NE + j0 + t];
#pragma unroll
        for (int b = 0; b < 16; b++) acc[b] += us[b * 256 + t] * wv;
    }
    float bv = ipb[2 * NE + row];
    for (int b = 0; b < 16; b++) {
        red[t] = acc[b];
        __syncthreads();
        for (int s = 128; s > 0; s >>= 1) {
            if (t < s) red[t] += red[t + s];
            __syncthreads();
        }
        if (t == 0) gY[b * NE + row] = red[0] + gSg[b * 4 + h] * bv;
        __syncthreads();
    }
}

// ---------------- out = y @ out_w^T + S*out_b ------------------------------------------
__global__ void __launch_bounds__(256) k_out(const float* __restrict__ out_w,
                                             const float* __restrict__ out_b,
                                             float* __restrict__ out) {
    const int e = blockIdx.x;
    const int t = threadIdx.x;
    __shared__ float ys[16 * 256];
    __shared__ float red[256];
    float acc[16];
#pragma unroll
    for (int b = 0; b < 16; b++) acc[b] = 0.f;
    for (int j0 = 0; j0 < NE; j0 += 256) {
        __syncthreads();
        for (int i = t; i < 16 * 256; i += 256) {
            int b = i >> 8, jj = i & 255;
            ys[i] = gY[b * NE + j0 + jj];
        }
        __syncthreads();
        float wv = out_w[(size_t)e * NE + j0 + t];
#pragma unroll
        for (int b = 0; b < 16; b++) acc[b] += ys[b * 256 + t] * wv;
    }
    for (int b = 0; b < 16; b++) {
        red[t] = acc[b];
        __syncthreads();
        for (int s = 128; s > 0; s >>= 1) {
            if (t < s) red[t] += red[t + s];
            __syncthreads();
        }
        if (t == 0) out[b * NE + e] = red[0] + 2048.0f * out_b[e];
        __syncthreads();
    }
}

// ---------------- launch ----------------------------------------------------------------
extern "C" void kernel_launch(void* const* d_in, const int* in_sizes, int n_in,
                              void* d_out, int out_size) {
    const float* x   = (const float*)d_in[0];
    const void*  msk = d_in[1];
    const float* ipw = (const float*)d_in[2];
    const float* ipb = (const float*)d_in[3];
    const float* ow  = (const float*)d_in[4];
    const float* ob  = (const float*)d_in[5];
    float* out = (float*)d_out;

    const int SMEM_GEMM = 4 * 16384;    // 64KB
    static bool attr_set = false;
    if (!attr_set) {
        cudaFuncSetAttribute(k_proj, cudaFuncAttributeMaxDynamicSharedMemorySize, SMEM_GEMM);
        cudaFuncSetAttribute(k_scores, cudaFuncAttributeMaxDynamicSharedMemorySize, SMEM_GEMM);
        attr_set = true;
    }

    k_zero_l<<<512, 256>>>();
    k_classify<<<1, 256>>>((const unsigned*)msk);
    k_convmask<<<128, 256>>>(msk);
    k_len<<<NB, 256>>>();

    k_conv<<<(int)(((size_t)NB * NS * NE + (size_t)2 * NE * NE) / 4 / 256), 256>>>(x, ipw);

    dim3 g1(16, 256);                   // N=2048/128, M=32768/128
    k_proj<<<g1, 256, SMEM_GEMM>>>(ipb);

    dim3 g2(16, 16, NBH);               // ktile, qtile, bh
    k_scores<<<g2, 256, SMEM_GEMM>>>();

    k_linv<<<512, 256>>>();

    dim3 g3(4, NBH);                    // 512 cols per block
    k_colsum<<<g3, 256>>>();
    k_cs<<<128, 256>>>();
    k_g<<<g3, 256>>>();

    dim3 g4(4, NB);
    k_u<<<g4, 256>>>(x);
    k_sg<<<NBH, 256>>>();
    k_yv<<<NE, 256>>>(ipw, ipb);
    k_out<<<NE, 256>>>(ow, ob, out);
}

// round 11
// speedup vs baseline: 1.0415x; 1.0044x over previous
#include <cuda_runtime.h>
#include <cuda_bf16.h>
#include <cstdint>

#define NB 16
#define NS 2048
#define NE 1024
#define NH 4
#define ND 256
#define NBH 64
#define BK 32

// ---------------- device scratch ------------------------------------------------
__device__ __align__(16) __nv_bfloat16 gXb[(size_t)NB * NS * NE];
__device__ __align__(16) __nv_bfloat16 gWb[(size_t)2 * NE * NE];
__device__ __align__(16) __nv_bfloat16 gQ[(size_t)NBH * NS * ND];   // scaled by 1/16
__device__ __align__(16) __nv_bfloat16 gK[(size_t)NBH * NS * ND];
__device__ __align__(16) __nv_bfloat16 gP[(size_t)NBH * NS * NS];   // exp(scores)
__device__ float gL[NBH * NS];
__device__ float gColsum[NBH * NS];
__device__ float gG[NBH * NS];
__device__ float gSg[NBH];
__device__ float gU[NBH * NE];
__device__ float gY[NB * NE];
__device__ unsigned char gValid[NB * NS];
__device__ int gLen[NB];

// ---------------- helpers ---------------------------------------------------------
__device__ __forceinline__ void cpa16(uint32_t s, const void* g) {
    asm volatile("cp.async.cg.shared.global [%0], [%1], 16;\n" :: "r"(s), "l"(g));
}
__device__ __forceinline__ void cp_commit() { asm volatile("cp.async.commit_group;\n"); }
template <int N>
__device__ __forceinline__ void cp_wait() { asm volatile("cp.async.wait_group %0;\n" :: "n"(N)); }

__device__ __forceinline__ void ldm4(uint32_t (&r)[4], uint32_t addr) {
    asm volatile("ldmatrix.sync.aligned.m8n8.x4.shared.b16 {%0,%1,%2,%3}, [%4];"
                 : "=r"(r[0]), "=r"(r[1]), "=r"(r[2]), "=r"(r[3]) : "r"(addr));
}

__device__ __forceinline__ void mma16816(float (&d)[4], const uint32_t (&a)[4],
                                         uint32_t b0, uint32_t b1) {
    asm volatile("mma.sync.aligned.m16n8k16.row.col.f32.bf16.bf16.f32 "
                 "{%0,%1,%2,%3}, {%4,%5,%6,%7}, {%8,%9}, {%0,%1,%2,%3};"
                 : "+f"(d[0]), "+f"(d[1]), "+f"(d[2]), "+f"(d[3])
                 : "r"(a[0]), "r"(a[1]), "r"(a[2]), "r"(a[3]), "r"(b0), "r"(b1));
}

// 64B-row swizzle: rows of 32 bf16, 4 chunks of 16B. chunk' = c ^ ((row>>1)&3)
__device__ __forceinline__ uint32_t swz64(uint32_t row, uint32_t c16) {
    return row * 64u + ((c16 ^ ((row >> 1) & 3u)) << 4);
}

// one pipeline stage: A 128x32 bf16 (8KB) + B 128x32 bf16 (8KB), 256 threads
__device__ __forceinline__ void load_stage(uint32_t sA, uint32_t sB,
                                           const __nv_bfloat16* __restrict__ Ag,
                                           const __nv_bfloat16* __restrict__ Bg,
                                           int lda, int tid) {
#pragma unroll
    for (int i = 0; i < 2; i++) {
        int ci = i * 256 + tid;
        uint32_t row = ci >> 2, c16 = ci & 3;
        cpa16(sA + swz64(row, c16), Ag + (size_t)row * lda + c16 * 8);
        cpa16(sB + swz64(row, c16), Bg + (size_t)row * lda + c16 * 8);
    }
}

// 128x128 block, 256 threads = 8 warps (2x4), warp tile 64x32, 4-stage pipeline.
// (Exact R4 core — run-validated.)
template <int KIT>
__device__ __forceinline__ void gemm_core(const __nv_bfloat16* __restrict__ A,
                                          const __nv_bfloat16* __restrict__ B,
                                          int lda, float (&c)[4][4][4], char* dsm) {
    uint32_t s0;
    asm("{ .reg .u64 t; cvta.to.shared.u64 t, %1; cvt.u32.u64 %0, t; }" : "=r"(s0) : "l"(dsm));
    const int tid = threadIdx.x, lane = tid & 31, warp = tid >> 5;
    const int wm = warp >> 2, wn = warp & 3;

#pragma unroll
    for (int s = 0; s < 3; s++) {
        if (s < KIT)
            load_stage(s0 + s * 16384, s0 + s * 16384 + 8192,
                       A + s * BK, B + s * BK, lda, tid);
        cp_commit();
    }

    for (int kt = 0; kt < KIT; kt++) {
        cp_wait<2>();
        __syncthreads();
        if (kt + 3 < KIT)
            load_stage(s0 + ((kt + 3) & 3) * 16384, s0 + ((kt + 3) & 3) * 16384 + 8192,
                       A + (size_t)(kt + 3) * BK, B + (size_t)(kt + 3) * BK, lda, tid);
        cp_commit();

        uint32_t aB = s0 + (kt & 3) * 16384;
        uint32_t bB = aB + 8192;
#pragma unroll
        for (int ks = 0; ks < 2; ks++) {
            uint32_t c16 = ks * 2 + (lane >> 4);
            uint32_t a[4][4];
#pragma unroll
            for (int mi = 0; mi < 4; mi++)
                ldm4(a[mi], aB + swz64(wm * 64 + mi * 16 + (lane & 15), c16));
            uint32_t b[4][2];
#pragma unroll
            for (int p = 0; p < 2; p++) {
                uint32_t q[4];
                ldm4(q, bB + swz64(wn * 32 + p * 16 + (lane & 15), c16));
                b[p * 2 + 0][0] = q[0]; b[p * 2 + 0][1] = q[2];
                b[p * 2 + 1][0] = q[1]; b[p * 2 + 1][1] = q[3];
            }
#pragma unroll
            for (int mi = 0; mi < 4; mi++)
#pragma unroll
                for (int ni = 0; ni < 4; ni++)
                    mma16816(c[mi][ni], a[mi], b[ni][0], b[ni][1]);
        }
    }
}

// ---------------- fused mask kernel: classify + convert + per-batch length ------------
// 16 blocks (one per batch); classification of the buffer encoding is recomputed
// redundantly per block (32KB scan — trivial).
__global__ void __launch_bounds__(256) k_mask(const void* __restrict__ m) {
    const int b = blockIdx.x;
    const int t = threadIdx.x;
    __shared__ int ok[3];
    __shared__ int scnt[256], smax[256];
    if (t < 3) ok[t] = 1;
    __syncthreads();
    const unsigned* mu = (const unsigned*)m;
    for (int i = t; i < 8192; i += 256) {
        unsigned v = mu[i];
        if (!(v == 0u || v == 1u)) ok[0] = 0;
        if (!(v == 0u || v == 0x3F800000u)) ok[1] = 0;
        unsigned lo = v & 0xFFFFu, hi = v >> 16;
        if (!((lo == 0u || lo == 0x3F80u) && (hi == 0u || hi == 0x3F80u))) ok[2] = 0;
    }
    __syncthreads();
    const int e = ok[0] ? 0 : (ok[1] ? 1 : (ok[2] ? 2 : 3));

    int cnt = 0, mx = -1;
    for (int i = t; i < NS; i += 256) {
        int gi = b * NS + i;
        unsigned char v;
        if (e == 0)      v = ((const int*)m)[gi] != 0;
        else if (e == 1) v = ((const float*)m)[gi] != 0.f;
        else if (e == 2) v = ((const unsigned short*)m)[gi] != 0;
        else             v = ((const unsigned char*)m)[gi] != 0;
        gValid[gi] = v;
        if (v) { cnt++; mx = i; }
    }
    scnt[t] = cnt; smax[t] = mx;
    __syncthreads();
    for (int s = 128; s > 0; s >>= 1) {
        if (t < s) {
            scnt[t] += scnt[t + s];
            smax[t] = max(smax[t], smax[t + s]);
        }
        __syncthreads();
    }
    if (t == 0) {
        int len = scnt[0];
        gLen[b] = (len > 0 && smax[0] == len - 1) ? len : NS;
    }
}

__global__ void k_zero_l() {
    int i = blockIdx.x * 256 + threadIdx.x;
    if (i < NBH * NS) gL[i] = 0.f;
}

// ---------------- fp32 -> bf16 conversion --------------------------------------------
__global__ void k_conv(const float* __restrict__ x, const float* __restrict__ w) {
    const size_t NX = (size_t)NB * NS * NE;
    const size_t NW = (size_t)2 * NE * NE;
    size_t i = ((size_t)blockIdx.x * 256 + threadIdx.x) * 4;
    if (i < NX) {
        float4 v = *(const float4*)(x + i);
        __nv_bfloat162* d = (__nv_bfloat162*)(gXb + i);
        d[0] = __floats2bfloat162_rn(v.x, v.y);
        d[1] = __floats2bfloat162_rn(v.z, v.w);
    } else {
        size_t j = i - NX;
        if (j < NW) {
            float4 v = *(const float4*)(w + j);
            __nv_bfloat162* d = (__nv_bfloat162*)(gWb + j);
            d[0] = __floats2bfloat162_rn(v.x, v.y);
            d[1] = __floats2bfloat162_rn(v.z, v.w);
        }
    }
}

// ---------------- GEMM1: Q/K projection (LAUNCH INDEX 3 — profiled slot) ---------------
__global__ void __launch_bounds__(256, 2) k_proj(const float* __restrict__ bias) {
    extern __shared__ char dsm[];
    const int bm = blockIdx.y * 128, bn = blockIdx.x * 128;
    const int which = bn >> 10;                 // 0=Q, 1=K
    const int bb = bm >> 11, ss = bm & 2047;
    if (which == 1 && ss >= gLen[bb]) return;   // masked K rows never read

    float c[4][4][4] = {};
    gemm_core<32>(gXb + (size_t)bm * 1024, gWb + (size_t)bn * 1024, 1024, c, dsm);

    const int lane = threadIdx.x & 31, warp = threadIdx.x >> 5;
    const int wm = warp >> 2, wn = warp & 3;
    const int g = lane >> 2, t2 = (lane & 3) * 2;
    const int h = (bn >> 8) & 3;
    __nv_bfloat16* dst = which ? gK : gQ;
    const float sc = which ? 1.0f : 0.0625f;    // fold 1/sqrt(256) into Q
#pragma unroll
    for (int mi = 0; mi < 4; mi++) {
#pragma unroll
        for (int half = 0; half < 2; half++) {
            int m = bm + wm * 64 + mi * 16 + g + half * 8;
            int b = m >> 11, s = m & 2047;
            __nv_bfloat16* drow = dst + ((size_t)(b * 4 + h) * NS + s) * ND;
#pragma unroll
            for (int ni = 0; ni < 4; ni++) {
                int n = bn + wn * 32 + ni * 8 + t2;
                float v0 = (c[mi][ni][half * 2 + 0] + bias[n]) * sc;
                float v1 = (c[mi][ni][half * 2 + 1] + bias[n + 1]) * sc;
                *(__nv_bfloat162*)(drow + (n & 255)) = __floats2bfloat162_rn(v0, v1);
            }
        }
    }
}

// ---------------- GEMM2: P = exp(Q K^T), mask, row sums ------------------------------
__global__ void __launch_bounds__(256, 2) k_scores() {
    extern __shared__ char dsm[];
    __shared__ float lrow[128];
    const int bh = blockIdx.z;
    const int bq = blockIdx.y * 128, bk = blockIdx.x * 128;
    const int bidx = bh >> 2;
    if (bk >= gLen[bidx]) return;               // fully-masked k-tile: skip
    if (threadIdx.x < 128) lrow[threadIdx.x] = 0.f;

    float c[4][4][4] = {};
    const __nv_bfloat16* Qb = gQ + ((size_t)bh * NS + bq) * ND;
    const __nv_bfloat16* Kb = gK + ((size_t)bh * NS + bk) * ND;
    gemm_core<8>(Qb, Kb, ND, c, dsm);

    const int lane = threadIdx.x & 31, warp = threadIdx.x >> 5;
    const int wm = warp >> 2, wn = warp & 3;
    const int g = lane >> 2, t2 = (lane & 3) * 2;

    unsigned char vm[4][2];
#pragma unroll
    for (int ni = 0; ni < 4; ni++) {
        int kc = bk + wn * 32 + ni * 8 + t2;
        vm[ni][0] = gValid[bidx * NS + kc];
        vm[ni][1] = gValid[bidx * NS + kc + 1];
    }
#pragma unroll
    for (int mi = 0; mi < 4; mi++) {
#pragma unroll
        for (int half = 0; half < 2; half++) {
            int qrow = wm * 64 + mi * 16 + g + half * 8;
            __nv_bfloat16* prow = gP + ((size_t)bh * NS + bq + qrow) * NS + bk + wn * 32;
            float rs = 0.f;
#pragma unroll
            for (int ni = 0; ni < 4; ni++) {
                float p0 = vm[ni][0] ? __expf(c[mi][ni][half * 2 + 0]) : 0.f;
                float p1 = vm[ni][1] ? __expf(c[mi][ni][half * 2 + 1]) : 0.f;
                rs += p0 + p1;
                *(__nv_bfloat162*)(prow + ni * 8 + t2) = __floats2bfloat162_rn(p0, p1);
            }
            rs += __shfl_xor_sync(0xFFFFFFFFu, rs, 1);
            rs += __shfl_xor_sync(0xFFFFFFFFu, rs, 2);
            if ((lane & 3) == 0) atomicAdd(&lrow[qrow], rs);
        }
    }
    __syncthreads();
    if (threadIdx.x < 128) atomicAdd(&gL[bh * NS + bq + threadIdx.x], lrow[threadIdx.x]);
}

// ---------------- column sums over P (1/l inlined) -------------------------------------
__global__ void __launch_bounds__(256) k_colsum() {
    const int bh = blockIdx.y;
    const int bidx = bh >> 2;
    const int len = gLen[bidx];
    const int lenR = (len + 127) & ~127;
    const int k = blockIdx.x * 512 + threadIdx.x * 2;
    __shared__ float ls[NS];
    for (int i = threadIdx.x; i < NS; i += 256) ls[i] = 1.0f / gL[bh * NS + i];
    __syncthreads();
    float2 out = {0.f, 0.f};
    if (k < lenR) {
        const __nv_bfloat16* Pc = gP + (size_t)bh * NS * NS + k;
        float a0 = 0, b0 = 0, a1 = 0, b1 = 0;
        for (int q = 0; q < NS; q += 2) {
            float2 v0 = __bfloat1622float2(*(const __nv_bfloat162*)(Pc + (size_t)q * NS));
            float2 v1 = __bfloat1622float2(*(const __nv_bfloat162*)(Pc + (size_t)(q + 1) * NS));
            a0 += v0.x * ls[q];     b0 += v0.y * ls[q];
            a1 += v1.x * ls[q + 1]; b1 += v1.y * ls[q + 1];
        }
        out.x = a0 + a1; out.y = b0 + b1;
    }
    gColsum[bh * NS + k] = out.x;
    gColsum[bh * NS + k + 1] = out.y;
}

// ---------------- g pass (cs and 1/l inlined into the weight prefetch) ------------------
__global__ void __launch_bounds__(256) k_g() {
    const int bh = blockIdx.y;
    const int bidx = bh >> 2;
    const int len = gLen[bidx];
    const int lenR = (len + 127) & ~127;
    const int k = blockIdx.x * 512 + threadIdx.x * 2;
    __shared__ float ws[NS];
    for (int i = threadIdx.x; i < NS; i += 256) {
        float cs = 0.25f * (gColsum[(bidx * 4 + 0) * NS + i] + gColsum[(bidx * 4 + 1) * NS + i] +
                            gColsum[(bidx * 4 + 2) * NS + i] + gColsum[(bidx * 4 + 3) * NS + i]);
        ws[i] = cs * (1.0f / gL[bh * NS + i]);
    }
    __syncthreads();
    float2 out = {0.f, 0.f};
    if (k < lenR) {
        const __nv_bfloat16* Pc = gP + (size_t)bh * NS * NS + k;
        float a0 = 0, b0 = 0, a1 = 0, b1 = 0;
        for (int q = 0; q < NS; q += 2) {
            float2 v0 = __bfloat1622float2(*(const __nv_bfloat162*)(Pc + (size_t)q * NS));
            float2 v1 = __bfloat1622float2(*(const __nv_bfloat162*)(Pc + (size_t)(q + 1) * NS));
            a0 += v0.x * ws[q];     b0 += v0.y * ws[q];
            a1 += v1.x * ws[q + 1]; b1 += v1.y * ws[q + 1];
        }
        out.x = a0 + a1; out.y = b0 + b1;
    }
    gG[bh * NS + k] = out.x;
    gG[bh * NS + k + 1] = out.y;
}

// ---------------- u[bh,e] = sum_k g[bh,k] x[b,k,e]  (fp32 x: precision-critical) ------
__global__ void __launch_bounds__(256) k_u(const float* __restrict__ x) {
    const int b = blockIdx.y;
    const int e = blockIdx.x * 256 + threadIdx.x;
    __shared__ float gs[4][NS];
    for (int i = threadIdx.x; i < 4 * NS; i += 256)
        gs[i >> 11][i & 2047] = gG[(b * 4 + (i >> 11)) * NS + (i & 2047)];
    __syncthreads();
    const int kend = (gLen[b] + 3) & ~3;
    float a0 = 0, a1 = 0, a2 = 0, a3 = 0;
    const float* xb = x + (size_t)b * NS * NE + e;
#pragma unroll 4
    for (int k = 0; k < kend; k++) {
        float xv = xb[(size_t)k * NE];
        a0 += gs[0][k] * xv; a1 += gs[1][k] * xv;
        a2 += gs[2][k] * xv; a3 += gs[3][k] * xv;
    }
    gU[(b * 4 + 0) * NE + e] = a0;
    gU[(b * 4 + 1) * NE + e] = a1;
    gU[(b * 4 + 2) * NE + e] = a2;
    gU[(b * 4 + 3) * NE + e] = a3;
}

__global__ void k_sg() {
    int bh = blockIdx.x;
    float s = 0.f;
    for (int k = threadIdx.x; k < NS; k += 256) s += gG[bh * NS + k];
    __shared__ float r[256];
    r[threadIdx.x] = s;
    __syncthreads();
    for (int st = 128; st > 0; st >>= 1) {
        if (threadIdx.x < st) r[threadIdx.x] += r[threadIdx.x + st];
        __syncthreads();
    }
    if (threadIdx.x == 0) gSg[bh] = r[0];
}

// ---------------- y = u @ Wv^T + sg*bv -------------------------------------------------
__global__ void __launch_bounds__(256) k_yv(const float* __restrict__ ipw,
                                            const float* __restrict__ ipb) {
    const int row = blockIdx.x;
    const int h = row >> 8;
    const int t = threadIdx.x;
    __shared__ float us[16 * 256];
    __shared__ float red[256];
    float acc[16];
#pragma unroll
    for (int b = 0; b < 16; b++) acc[b] = 0.f;
    for (int j0 = 0; j0 < NE; j0 += 256) {
        __syncthreads();
        for (int i = t; i < 16 * 256; i += 256) {
            int b = i >> 8, jj = i & 255;
            us[i] = gU[(b * 4 + h) * NE + j0 + jj];
        }
        __syncthreads();
        float wv = ipw[(size_t)(2 * NE + row) * NE + j0 + t];
#pragma unroll
        for (int b = 0; b < 16; b++) acc[b] += us[b * 256 + t] * wv;
    }
    float bv = ipb[2 * NE + row];
    for (int b = 0; b < 16; b++) {
        red[t] = acc[b];
        __syncthreads();
        for (int s = 128; s > 0; s >>= 1) {
            if (t < s) red[t] += red[t + s];
            __syncthreads();
        }
        if (t == 0) gY[b * NE + row] = red[0] + gSg[b * 4 + h] * bv;
        __syncthreads();
    }
}

// ---------------- out = y @ out_w^T + S*out_b ------------------------------------------
__global__ void __launch_bounds__(256) k_out(const float* __restrict__ out_w,
                                             const float* __restrict__ out_b,
                                             float* __restrict__ out) {
    const int e = blockIdx.x;
    const int t = threadIdx.x;
    __shared__ float ys[16 * 256];
    __shared__ float red[256];
    float acc[16];
#pragma unroll
    for (int b = 0; b < 16; b++) acc[b] = 0.f;
    for (int j0 = 0; j0 < NE; j0 += 256) {
        __syncthreads();
        for (int i = t; i < 16 * 256; i += 256) {
            int b = i >> 8, jj = i & 255;
            ys[i] = gY[b * NE + j0 + jj];
        }
        __syncthreads();
        float wv = out_w[(size_t)e * NE + j0 + t];
#pragma unroll
        for (int b = 0; b < 16; b++) acc[b] += ys[b * 256 + t] * wv;
    }
    for (int b = 0; b < 16; b++) {
        red[t] = acc[b];
        __syncthreads();
        for (int s = 128; s > 0; s >>= 1) {
            if (t < s) red[t] += red[t + s];
            __syncthreads();
        }
        if (t == 0) out[b * NE + e] = red[0] + 2048.0f * out_b[e];
        __syncthreads();
    }
}

// ---------------- launch ----------------------------------------------------------------
extern "C" void kernel_launch(void* const* d_in, const int* in_sizes, int n_in,
                              void* d_out, int out_size) {
    const float* x   = (const float*)d_in[0];
    const void*  msk = d_in[1];
    const float* ipw = (const float*)d_in[2];
    const float* ipb = (const float*)d_in[3];
    const float* ow  = (const float*)d_in[4];
    const float* ob  = (const float*)d_in[5];
    float* out = (float*)d_out;

    const int SMEM_GEMM = 4 * 16384;    // 64KB
    static bool attr_set = false;
    if (!attr_set) {
        cudaFuncSetAttribute(k_proj, cudaFuncAttributeMaxDynamicSharedMemorySize, SMEM_GEMM);
        cudaFuncSetAttribute(k_scores, cudaFuncAttributeMaxDynamicSharedMemorySize, SMEM_GEMM);
        attr_set = true;
    }

    // Launch order matters for profiling: the ncu capture samples launch index 3,
    // so k_proj is placed 4th.
    k_conv<<<(int)(((size_t)NB * NS * NE + (size_t)2 * NE * NE) / 4 / 256), 256>>>(x, ipw);  // 0
    k_mask<<<NB, 256>>>(msk);                                                                // 1
    k_zero_l<<<512, 256>>>();                                                                // 2

    dim3 g1(16, 256);                   // N=2048/128, M=32768/128
    k_proj<<<g1, 256, SMEM_GEMM>>>(ipb);                                                     // 3 <- profiled

    dim3 g2(16, 16, NBH);               // ktile, qtile, bh
    k_scores<<<g2, 256, SMEM_GEMM>>>();

    dim3 g3(4, NBH);                    // 512 cols per block
    k_colsum<<<g3, 256>>>();
    k_g<<<g3, 256>>>();

    dim3 g4(4, NB);
    k_u<<<g4, 256>>>(x);
    k_sg<<<NBH, 256>>>();
    k_yv<<<NE, 256>>>(ipw, ipb);
    k_out<<<NE, 256>>>(ow, ob, out);
}

// round 12
// speedup vs baseline: 1.0713x; 1.0286x over previous
#include <cuda_runtime.h>
#include <cuda_bf16.h>
#include <cstdint>

#define NB 16
#define NS 2048
#define NE 1024
#define NH 4
#define ND 256
#define NBH 64
#define BK 32

// ---------------- device scratch ------------------------------------------------
__device__ __align__(16) __nv_bfloat16 gXb[(size_t)NB * NS * NE];
__device__ __align__(16) __nv_bfloat16 gWb[(size_t)2 * NE * NE];
__device__ __align__(16) __nv_bfloat16 gQ[(size_t)NBH * NS * ND];   // scaled by 1/16
__device__ __align__(16) __nv_bfloat16 gK[(size_t)NBH * NS * ND];
__device__ __align__(16) __nv_bfloat16 gP[(size_t)NBH * NS * NS];   // exp(scores)
__device__ float gL[NBH * NS];
__device__ float gColsum[NBH * NS];
__device__ float gG[NBH * NS];
__device__ float gSg[NBH];
__device__ float gU[NBH * NE];
__device__ float gY[NB * NE];
__device__ unsigned char gValid[NB * NS];
__device__ int gLen[NB];

// ---------------- helpers ---------------------------------------------------------
__device__ __forceinline__ void cpa16(uint32_t s, const void* g) {
    asm volatile("cp.async.cg.shared.global [%0], [%1], 16;\n" :: "r"(s), "l"(g));
}
__device__ __forceinline__ void cp_commit() { asm volatile("cp.async.commit_group;\n"); }
template <int N>
__device__ __forceinline__ void cp_wait() { asm volatile("cp.async.wait_group %0;\n" :: "n"(N)); }

__device__ __forceinline__ void ldm4(uint32_t (&r)[4], uint32_t addr) {
    asm volatile("ldmatrix.sync.aligned.m8n8.x4.shared.b16 {%0,%1,%2,%3}, [%4];"
                 : "=r"(r[0]), "=r"(r[1]), "=r"(r[2]), "=r"(r[3]) : "r"(addr));
}

__device__ __forceinline__ void mma16816(float (&d)[4], const uint32_t (&a)[4],
                                         uint32_t b0, uint32_t b1) {
    asm volatile("mma.sync.aligned.m16n8k16.row.col.f32.bf16.bf16.f32 "
                 "{%0,%1,%2,%3}, {%4,%5,%6,%7}, {%8,%9}, {%0,%1,%2,%3};"
                 : "+f"(d[0]), "+f"(d[1]), "+f"(d[2]), "+f"(d[3])
                 : "r"(a[0]), "r"(a[1]), "r"(a[2]), "r"(a[3]), "r"(b0), "r"(b1));
}

// 64B-row swizzle: rows of 32 bf16, 4 chunks of 16B. chunk' = c ^ ((row>>1)&3)
__device__ __forceinline__ uint32_t swz64(uint32_t row, uint32_t c16) {
    return row * 64u + ((c16 ^ ((row >> 1) & 3u)) << 4);
}

// one pipeline stage: A 128x32 bf16 (8KB) + B 128x32 bf16 (8KB), 256 threads
__device__ __forceinline__ void load_stage(uint32_t sA, uint32_t sB,
                                           const __nv_bfloat16* __restrict__ Ag,
                                           const __nv_bfloat16* __restrict__ Bg,
                                           int lda, int tid) {
#pragma unroll
    for (int i = 0; i < 2; i++) {
        int ci = i * 256 + tid;
        uint32_t row = ci >> 2, c16 = ci & 3;
        cpa16(sA + swz64(row, c16), Ag + (size_t)row * lda + c16 * 8);
        cpa16(sB + swz64(row, c16), Bg + (size_t)row * lda + c16 * 8);
    }
}

// 128x128 block, 256 threads = 8 warps (2x4), warp tile 64x32, 4-stage pipeline.
// (Exact R4 core — run-validated.)
template <int KIT>
__device__ __forceinline__ void gemm_core(const __nv_bfloat16* __restrict__ A,
                                          const __nv_bfloat16* __restrict__ B,
                                          int lda, float (&c)[4][4][4], char* dsm) {
    uint32_t s0;
    asm("{ .reg .u64 t; cvta.to.shared.u64 t, %1; cvt.u32.u64 %0, t; }" : "=r"(s0) : "l"(dsm));
    const int tid = threadIdx.x, lane = tid & 31, warp = tid >> 5;
    const int wm = warp >> 2, wn = warp & 3;

#pragma unroll
    for (int s = 0; s < 3; s++) {
        if (s < KIT)
            load_stage(s0 + s * 16384, s0 + s * 16384 + 8192,
                       A + s * BK, B + s * BK, lda, tid);
        cp_commit();
    }

    for (int kt = 0; kt < KIT; kt++) {
        cp_wait<2>();
        __syncthreads();
        if (kt + 3 < KIT)
            load_stage(s0 + ((kt + 3) & 3) * 16384, s0 + ((kt + 3) & 3) * 16384 + 8192,
                       A + (size_t)(kt + 3) * BK, B + (size_t)(kt + 3) * BK, lda, tid);
        cp_commit();

        uint32_t aB = s0 + (kt & 3) * 16384;
        uint32_t bB = aB + 8192;
#pragma unroll
        for (int ks = 0; ks < 2; ks++) {
            uint32_t c16 = ks * 2 + (lane >> 4);
            uint32_t a[4][4];
#pragma unroll
            for (int mi = 0; mi < 4; mi++)
                ldm4(a[mi], aB + swz64(wm * 64 + mi * 16 + (lane & 15), c16));
            uint32_t b[4][2];
#pragma unroll
            for (int p = 0; p < 2; p++) {
                uint32_t q[4];
                ldm4(q, bB + swz64(wn * 32 + p * 16 + (lane & 15), c16));
                b[p * 2 + 0][0] = q[0]; b[p * 2 + 0][1] = q[2];
                b[p * 2 + 1][0] = q[1]; b[p * 2 + 1][1] = q[3];
            }
#pragma unroll
            for (int mi = 0; mi < 4; mi++)
#pragma unroll
                for (int ni = 0; ni < 4; ni++)
                    mma16816(c[mi][ni], a[mi], b[ni][0], b[ni][1]);
        }
    }
}

// ---------------- fused mask kernel: classify + convert + length + zero gL ------------
__global__ void __launch_bounds__(256) k_mask(const void* __restrict__ m) {
    const int b = blockIdx.x;
    const int t = threadIdx.x;
    __shared__ int ok[3];
    __shared__ int scnt[256], smax[256];
    if (t < 3) ok[t] = 1;
    __syncthreads();
    const unsigned* mu = (const unsigned*)m;
    for (int i = t; i < 8192; i += 256) {
        unsigned v = mu[i];
        if (!(v == 0u || v == 1u)) ok[0] = 0;
        if (!(v == 0u || v == 0x3F800000u)) ok[1] = 0;
        unsigned lo = v & 0xFFFFu, hi = v >> 16;
        if (!((lo == 0u || lo == 0x3F80u) && (hi == 0u || hi == 0x3F80u))) ok[2] = 0;
    }
    __syncthreads();
    const int e = ok[0] ? 0 : (ok[1] ? 1 : (ok[2] ? 2 : 3));

    // zero gL slice (fused former k_zero_l)
    for (int i = t; i < 8192; i += 256) gL[b * 8192 + i] = 0.f;

    int cnt = 0, mx = -1;
    for (int i = t; i < NS; i += 256) {
        int gi = b * NS + i;
        unsigned char v;
        if (e == 0)      v = ((const int*)m)[gi] != 0;
        else if (e == 1) v = ((const float*)m)[gi] != 0.f;
        else if (e == 2) v = ((const unsigned short*)m)[gi] != 0;
        else             v = ((const unsigned char*)m)[gi] != 0;
        gValid[gi] = v;
        if (v) { cnt++; mx = i; }
    }
    scnt[t] = cnt; smax[t] = mx;
    __syncthreads();
    for (int s = 128; s > 0; s >>= 1) {
        if (t < s) {
            scnt[t] += scnt[t + s];
            smax[t] = max(smax[t], smax[t + s]);
        }
        __syncthreads();
    }
    if (t == 0) {
        int len = scnt[0];
        gLen[b] = (len > 0 && smax[0] == len - 1) ? len : NS;
    }
}

// ---------------- fp32 -> bf16 conversion --------------------------------------------
__global__ void k_conv(const float* __restrict__ x, const float* __restrict__ w) {
    const size_t NX = (size_t)NB * NS * NE;
    const size_t NW = (size_t)2 * NE * NE;
    size_t i = ((size_t)blockIdx.x * 256 + threadIdx.x) * 4;
    if (i < NX) {
        float4 v = *(const float4*)(x + i);
        __nv_bfloat162* d = (__nv_bfloat162*)(gXb + i);
        d[0] = __floats2bfloat162_rn(v.x, v.y);
        d[1] = __floats2bfloat162_rn(v.z, v.w);
    } else {
        size_t j = i - NX;
        if (j < NW) {
            float4 v = *(const float4*)(w + j);
            __nv_bfloat162* d = (__nv_bfloat162*)(gWb + j);
            d[0] = __floats2bfloat162_rn(v.x, v.y);
            d[1] = __floats2bfloat162_rn(v.z, v.w);
        }
    }
}

// ---------------- GEMM1: Q/K projection ------------------------------------------------
__global__ void __launch_bounds__(256, 2) k_proj(const float* __restrict__ bias) {
    extern __shared__ char dsm[];
    const int bm = blockIdx.y * 128, bn = blockIdx.x * 128;
    const int which = bn >> 10;                 // 0=Q, 1=K
    const int bb = bm >> 11, ss = bm & 2047;
    if (which == 1 && ss >= gLen[bb]) return;   // masked K rows never read

    float c[4][4][4] = {};
    gemm_core<32>(gXb + (size_t)bm * 1024, gWb + (size_t)bn * 1024, 1024, c, dsm);

    const int lane = threadIdx.x & 31, warp = threadIdx.x >> 5;
    const int wm = warp >> 2, wn = warp & 3;
    const int g = lane >> 2, t2 = (lane & 3) * 2;
    const int h = (bn >> 8) & 3;
    __nv_bfloat16* dst = which ? gK : gQ;
    const float sc = which ? 1.0f : 0.0625f;    // fold 1/sqrt(256) into Q
#pragma unroll
    for (int mi = 0; mi < 4; mi++) {
#pragma unroll
        for (int half = 0; half < 2; half++) {
            int m = bm + wm * 64 + mi * 16 + g + half * 8;
            int b = m >> 11, s = m & 2047;
            __nv_bfloat16* drow = dst + ((size_t)(b * 4 + h) * NS + s) * ND;
#pragma unroll
            for (int ni = 0; ni < 4; ni++) {
                int n = bn + wn * 32 + ni * 8 + t2;
                float v0 = (c[mi][ni][half * 2 + 0] + bias[n]) * sc;
                float v1 = (c[mi][ni][half * 2 + 1] + bias[n + 1]) * sc;
                *(__nv_bfloat162*)(drow + (n & 255)) = __floats2bfloat162_rn(v0, v1);
            }
        }
    }
}

// ---------------- GEMM2: P = exp(Q K^T), mask, row sums (LAUNCH 3 — profiled) ---------
// Epilogue stages the bf16 tile in smem (XOR-swizzled, conflict-free) and copies
// out with fully-coalesced 256B-per-row stores instead of scattered 4B STGs.
__global__ void __launch_bounds__(256, 2) k_scores() {
    extern __shared__ char dsm[];
    __shared__ float lrow[128];
    const int bh = blockIdx.z;
    const int bq = blockIdx.y * 128, bk = blockIdx.x * 128;
    const int bidx = bh >> 2;
    if (bk >= gLen[bidx]) return;               // fully-masked k-tile: skip
    if (threadIdx.x < 128) lrow[threadIdx.x] = 0.f;

    float c[4][4][4] = {};
    const __nv_bfloat16* Qb = gQ + ((size_t)bh * NS + bq) * ND;
    const __nv_bfloat16* Kb = gK + ((size_t)bh * NS + bk) * ND;
    gemm_core<8>(Qb, Kb, ND, c, dsm);

    // drain async pipe before reusing dsm as a staging buffer
    cp_wait<0>();
    __syncthreads();

    const int lane = threadIdx.x & 31, warp = threadIdx.x >> 5;
    const int wm = warp >> 2, wn = warp & 3;
    const int g = lane >> 2, t2 = (lane & 3) * 2;

    unsigned char vm[4][2];
#pragma unroll
    for (int ni = 0; ni < 4; ni++) {
        int kc = bk + wn * 32 + ni * 8 + t2;
        vm[ni][0] = gValid[bidx * NS + kc];
        vm[ni][1] = gValid[bidx * NS + kc + 1];
    }
#pragma unroll
    for (int mi = 0; mi < 4; mi++) {
#pragma unroll
        for (int half = 0; half < 2; half++) {
            int qrow = wm * 64 + mi * 16 + g + half * 8;
            float rs = 0.f;
#pragma unroll
            for (int ni = 0; ni < 4; ni++) {
                float p0 = vm[ni][0] ? __expf(c[mi][ni][half * 2 + 0]) : 0.f;
                float p1 = vm[ni][1] ? __expf(c[mi][ni][half * 2 + 1]) : 0.f;
                rs += p0 + p1;
                // stage bf16x2 into smem: row stride 256B, 16B-chunk XOR swizzle
                uint32_t c16 = (uint32_t)(wn * 4 + ni);
                uint32_t off = (uint32_t)qrow * 256u +
                               ((c16 ^ ((uint32_t)qrow & 7u)) << 4) + (lane & 3) * 4;
                *(__nv_bfloat162*)(dsm + off) = __floats2bfloat162_rn(p0, p1);
            }
            rs += __shfl_xor_sync(0xFFFFFFFFu, rs, 1);
            rs += __shfl_xor_sync(0xFFFFFFFFu, rs, 2);
            if ((lane & 3) == 0) atomicAdd(&lrow[qrow], rs);
        }
    }
    __syncthreads();
    if (threadIdx.x < 128) atomicAdd(&gL[bh * NS + bq + threadIdx.x], lrow[threadIdx.x]);

    // coalesced copy-out: 16 lanes x 16B = 256B contiguous per row
    const int rrow = threadIdx.x >> 4;          // 0..15
    const uint32_t cc = threadIdx.x & 15;       // chunk 0..15
#pragma unroll
    for (int it = 0; it < 8; it++) {
        int r = it * 16 + rrow;
        uint32_t soff = (uint32_t)r * 256u + ((cc ^ ((uint32_t)r & 7u)) << 4);
        uint4 v = *(const uint4*)(dsm + soff);
        *(uint4*)(gP + ((size_t)bh * NS + bq + r) * NS + bk + cc * 8) = v;
    }
}

// ---------------- column sums over P (1/l inlined) -------------------------------------
__global__ void __launch_bounds__(256) k_colsum() {
    const int bh = blockIdx.y;
    const int bidx = bh >> 2;
    const int len = gLen[bidx];
    const int lenR = (len + 127) & ~127;
    const int k = blockIdx.x * 512 + threadIdx.x * 2;
    __shared__ float ls[NS];
    for (int i = threadIdx.x; i < NS; i += 256) ls[i] = 1.0f / gL[bh * NS + i];
    __syncthreads();
    float2 out = {0.f, 0.f};
    if (k < lenR) {
        const __nv_bfloat16* Pc = gP + (size_t)bh * NS * NS + k;
        float a0 = 0, b0 = 0, a1 = 0, b1 = 0;
        for (int q = 0; q < NS; q += 2) {
            float2 v0 = __bfloat1622float2(*(const __nv_bfloat162*)(Pc + (size_t)q * NS));
            float2 v1 = __bfloat1622float2(*(const __nv_bfloat162*)(Pc + (size_t)(q + 1) * NS));
            a0 += v0.x * ls[q];     b0 += v0.y * ls[q];
            a1 += v1.x * ls[q + 1]; b1 += v1.y * ls[q + 1];
        }
        out.x = a0 + a1; out.y = b0 + b1;
    }
    gColsum[bh * NS + k] = out.x;
    gColsum[bh * NS + k + 1] = out.y;
}

// ---------------- g pass (cs and 1/l inlined into the weight prefetch) ------------------
__global__ void __launch_bounds__(256) k_g() {
    const int bh = blockIdx.y;
    const int bidx = bh >> 2;
    const int len = gLen[bidx];
    const int lenR = (len + 127) & ~127;
    const int k = blockIdx.x * 512 + threadIdx.x * 2;
    __shared__ float ws[NS];
    for (int i = threadIdx.x; i < NS; i += 256) {
        float cs = 0.25f * (gColsum[(bidx * 4 + 0) * NS + i] + gColsum[(bidx * 4 + 1) * NS + i] +
                            gColsum[(bidx * 4 + 2) * NS + i] + gColsum[(bidx * 4 + 3) * NS + i]);
        ws[i] = cs * (1.0f / gL[bh * NS + i]);
    }
    __syncthreads();
    float2 out = {0.f, 0.f};
    if (k < lenR) {
        const __nv_bfloat16* Pc = gP + (size_t)bh * NS * NS + k;
        float a0 = 0, b0 = 0, a1 = 0, b1 = 0;
        for (int q = 0; q < NS; q += 2) {
            float2 v0 = __bfloat1622float2(*(const __nv_bfloat162*)(Pc + (size_t)q * NS));
            float2 v1 = __bfloat1622float2(*(const __nv_bfloat162*)(Pc + (size_t)(q + 1) * NS));
            a0 += v0.x * ws[q];     b0 += v0.y * ws[q];
            a1 += v1.x * ws[q + 1]; b1 += v1.y * ws[q + 1];
        }
        out.x = a0 + a1; out.y = b0 + b1;
    }
    gG[bh * NS + k] = out.x;
    gG[bh * NS + k + 1] = out.y;
}

// ---------------- u[bh,e] = sum_k g[bh,k] x[b,k,e]  (fp32 x: precision-critical) ------
__global__ void __launch_bounds__(256) k_u(const float* __restrict__ x) {
    const int b = blockIdx.y;
    const int e = blockIdx.x * 256 + threadIdx.x;
    __shared__ float gs[4][NS];
    for (int i = threadIdx.x; i < 4 * NS; i += 256)
        gs[i >> 11][i & 2047] = gG[(b * 4 + (i >> 11)) * NS + (i & 2047)];
    __syncthreads();
    const int kend = (gLen[b] + 3) & ~3;
    float a0 = 0, a1 = 0, a2 = 0, a3 = 0;
    const float* xb = x + (size_t)b * NS * NE + e;
#pragma unroll 4
    for (int k = 0; k < kend; k++) {
        float xv = xb[(size_t)k * NE];
        a0 += gs[0][k] * xv; a1 += gs[1][k] * xv;
        a2 += gs[2][k] * xv; a3 += gs[3][k] * xv;
    }
    gU[(b * 4 + 0) * NE + e] = a0;
    gU[(b * 4 + 1) * NE + e] = a1;
    gU[(b * 4 + 2) * NE + e] = a2;
    gU[(b * 4 + 3) * NE + e] = a3;
}

__global__ void k_sg() {
    int bh = blockIdx.x;
    float s = 0.f;
    for (int k = threadIdx.x; k < NS; k += 256) s += gG[bh * NS + k];
    __shared__ float r[256];
    r[threadIdx.x] = s;
    __syncthreads();
    for (int st = 128; st > 0; st >>= 1) {
        if (threadIdx.x < st) r[threadIdx.x] += r[threadIdx.x + st];
        __syncthreads();
    }
    if (threadIdx.x == 0) gSg[bh] = r[0];
}

// ---------------- y = u @ Wv^T + sg*bv -------------------------------------------------
__global__ void __launch_bounds__(256) k_yv(const float* __restrict__ ipw,
                                            const float* __restrict__ ipb) {
    const int row = blockIdx.x;
    const int h = row >> 8;
    const int t = threadIdx.x;
    __shared__ float us[16 * 256];
    __shared__ float red[256];
    float acc[16];
#pragma unroll
    for (int b = 0; b < 16; b++) acc[b] = 0.f;
    for (int j0 = 0; j0 < NE; j0 += 256) {
        __syncthreads();
        for (int i = t; i < 16 * 256; i += 256) {
            int b = i >> 8, jj = i & 255;
            us[i] = gU[(b * 4 + h) * NE + j0 + jj];
        }
        __syncthreads();
        float wv = ipw[(size_t)(2 * NE + row) * NE + j0 + t];
#pragma unroll
        for (int b = 0; b < 16; b++) acc[b] += us[b * 256 + t] * wv;
    }
    float bv = ipb[2 * NE + row];
    for (int b = 0; b < 16; b++) {
        red[t] = acc[b];
        __syncthreads();
        for (int s = 128; s > 0; s >>= 1) {
            if (t < s) red[t] += red[t + s];
            __syncthreads();
        }
        if (t == 0) gY[b * NE + row] = red[0] + gSg[b * 4 + h] * bv;
        __syncthreads();
    }
}

// ---------------- out = y @ out_w^T + S*out_b ------------------------------------------
__global__ void __launch_bounds__(256) k_out(const float* __restrict__ out_w,
                                             const float* __restrict__ out_b,
                                             float* __restrict__ out) {
    const int e = blockIdx.x;
    const int t = threadIdx.x;
    __shared__ float ys[16 * 256];
    __shared__ float red[256];
    float acc[16];
#pragma unroll
    for (int b = 0; b < 16; b++) acc[b] = 0.f;
    for (int j0 = 0; j0 < NE; j0 += 256) {
        __syncthreads();
        for (int i = t; i < 16 * 256; i += 256) {
            int b = i >> 8, jj = i & 255;
            ys[i] = gY[b * NE + j0 + jj];
        }
        __syncthreads();
        float wv = out_w[(size_t)e * NE + j0 + t];
#pragma unroll
        for (int b = 0; b < 16; b++) acc[b] += ys[b * 256 + t] * wv;
    }
    for (int b = 0; b < 16; b++) {
        red[t] = acc[b];
        __syncthreads();
        for (int s = 128; s > 0; s >>= 1) {
            if (t < s) red[t] += red[t + s];
            __syncthreads();
        }
        if (t == 0) out[b * NE + e] = red[0] + 2048.0f * out_b[e];
        __syncthreads();
    }
}

// ---------------- launch ----------------------------------------------------------------
extern "C" void kernel_launch(void* const* d_in, const int* in_sizes, int n_in,
                              void* d_out, int out_size) {
    const float* x   = (const float*)d_in[0];
    const void*  msk = d_in[1];
    const float* ipw = (const float*)d_in[2];
    const float* ipb = (const float*)d_in[3];
    const float* ow  = (const float*)d_in[4];
    const float* ob  = (const float*)d_in[5];
    float* out = (float*)d_out;

    const int SMEM_GEMM = 4 * 16384;    // 64KB
    static bool attr_set = false;
    if (!attr_set) {
        cudaFuncSetAttribute(k_proj, cudaFuncAttributeMaxDynamicSharedMemorySize, SMEM_GEMM);
        cudaFuncSetAttribute(k_scores, cudaFuncAttributeMaxDynamicSharedMemorySize, SMEM_GEMM);
        attr_set = true;
    }

    // ncu samples launch index 3 -> k_scores is placed 4th.
    k_conv<<<(int)(((size_t)NB * NS * NE + (size_t)2 * NE * NE) / 4 / 256), 256>>>(x, ipw);  // 0
    k_mask<<<NB, 256>>>(msk);                                                                // 1

    dim3 g1(16, 256);                   // N=2048/128, M=32768/128
    k_proj<<<g1, 256, SMEM_GEMM>>>(ipb);                                                     // 2

    dim3 g2(16, 16, NBH);               // ktile, qtile, bh
    k_scores<<<g2, 256, SMEM_GEMM>>>();                                                      // 3 <- profiled

    dim3 g3(4, NBH);                    // 512 cols per block
    k_colsum<<<g3, 256>>>();
    k_g<<<g3, 256>>>();

    dim3 g4(4, NB);
    k_u<<<g4, 256>>>(x);
    k_sg<<<NBH, 256>>>();
    k_yv<<<NE, 256>>>(ipw, ipb);
    k_out<<<NE, 256>>>(ow, ob, out);
}